// round 2
// baseline (speedup 1.0000x reference)
#include <cuda_runtime.h>
#include <math.h>

#define BB 4
#define LL 2048
#define DDM 1024
#define HH 16
#define NT (BB*LL)   // 8192 tokens

// ---------------- scratch (device globals: allocation-free rule) ----------------
__device__ float g_ln[(size_t)NT * DDM];          // 32 MB
__device__ float g_qkv[(size_t)NT * 3 * DDM];     // 96 MB
__device__ float g_ctx[(size_t)NT * DDM];         // 32 MB
__device__ float g_cs[LL * 32];                   // rope cos table
__device__ float g_sn[LL * 32];                   // rope sin table
__device__ int   g_sid[NT];                       // normalized sequence ids

// ---------------- sequence_id dtype sniff + normalize ----------------
// Reference casts to int64 under JAX; with x64 disabled that materializes as
// int32. Handle both: int64 little-endian layout has all-zero high words at
// probe positions; genuine int32 sorted data is nonzero there w.p. ~1.
__global__ void sid_norm_kernel(const void* __restrict__ seqraw) {
    const int* w = (const int*)seqraw;
    bool is64 = (w[2*1000+1] == 0) && (w[2*1500+1] == 0) && (w[2*2047+1] == 0);
    int i = blockIdx.x * blockDim.x + threadIdx.x;
    if (i < NT) g_sid[i] = is64 ? w[2*i] : w[i];
}

// ---------------- rope tables (fp64 for angle accuracy at s up to 2048) ----------------
__global__ void rope_table_kernel() {
    int idx = blockIdx.x * blockDim.x + threadIdx.x;
    if (idx >= LL * 32) return;
    int s = idx >> 5, i = idx & 31;
    double ang = (double)s * pow(10000.0, -(double)i / 32.0);
    g_cs[idx] = (float)cos(ang);
    g_sn[idx] = (float)sin(ang);
}

// ---------------- input LayerNorm (w, b) ----------------
__global__ void __launch_bounds__(256) ln_kernel(
    const float* __restrict__ x, const float* __restrict__ w, const float* __restrict__ b) {
    int row = blockIdx.x;
    int tid = threadIdx.x;
    float4 v = ((const float4*)(x + (size_t)row * DDM))[tid];
    float s  = v.x + v.y + v.z + v.w;
    float ss = v.x*v.x + v.y*v.y + v.z*v.z + v.w*v.w;
    __shared__ float rs[8], rss[8];
#pragma unroll
    for (int o = 16; o; o >>= 1) {
        s  += __shfl_xor_sync(0xffffffffu, s,  o);
        ss += __shfl_xor_sync(0xffffffffu, ss, o);
    }
    if ((tid & 31) == 0) { rs[tid >> 5] = s; rss[tid >> 5] = ss; }
    __syncthreads();
    if (tid == 0) {
        float a = 0.f, c = 0.f;
#pragma unroll
        for (int i = 0; i < 8; i++) { a += rs[i]; c += rss[i]; }
        rs[0] = a; rss[0] = c;
    }
    __syncthreads();
    float mean = rs[0] * (1.0f / DDM);
    float var  = rss[0] * (1.0f / DDM) - mean * mean;
    float rstd = rsqrtf(var + 1e-5f);
    float4 wv = ((const float4*)w)[tid];
    float4 bv = ((const float4*)b)[tid];
    float4 o;
    o.x = (v.x - mean) * rstd * wv.x + bv.x;
    o.y = (v.y - mean) * rstd * wv.y + bv.y;
    o.z = (v.z - mean) * rstd * wv.z + bv.z;
    o.w = (v.w - mean) * rstd * wv.w + bv.w;
    ((float4*)(g_ln + (size_t)row * DDM))[tid] = o;
}

// ---------------- QK LayerNorm (scale-only) + RoPE, in place on g_qkv ----------------
__global__ void __launch_bounds__(256) qkln_rope_kernel(
    const float* __restrict__ qw, const float* __restrict__ kw) {
    int token = blockIdx.x;
    int tid = threadIdx.x;
    int s = token & (LL - 1);            // position within L
    __shared__ float buf[DDM];
    __shared__ float rs[8], rss[8];
    for (int pass = 0; pass < 2; pass++) {
        float* rowp = g_qkv + (size_t)token * 3 * DDM + pass * DDM;
        const float* w = pass ? kw : qw;
        float4 v = ((const float4*)rowp)[tid];
        float sm = v.x + v.y + v.z + v.w;
        float sq = v.x*v.x + v.y*v.y + v.z*v.z + v.w*v.w;
#pragma unroll
        for (int o = 16; o; o >>= 1) {
            sm += __shfl_xor_sync(0xffffffffu, sm, o);
            sq += __shfl_xor_sync(0xffffffffu, sq, o);
        }
        if ((tid & 31) == 0) { rs[tid >> 5] = sm; rss[tid >> 5] = sq; }
        __syncthreads();
        if (tid == 0) {
            float a = 0.f, c = 0.f;
#pragma unroll
            for (int i = 0; i < 8; i++) { a += rs[i]; c += rss[i]; }
            rs[0] = a; rss[0] = c;
        }
        __syncthreads();
        float mean = rs[0] * (1.0f / DDM);
        float var  = rss[0] * (1.0f / DDM) - mean * mean;
        float rstd = rsqrtf(var + 1e-5f);
        float4 wv = ((const float4*)w)[tid];
        int c0 = tid * 4;
        buf[c0 + 0] = (v.x - mean) * rstd * wv.x;
        buf[c0 + 1] = (v.y - mean) * rstd * wv.y;
        buf[c0 + 2] = (v.z - mean) * rstd * wv.z;
        buf[c0 + 3] = (v.w - mean) * rstd * wv.w;
        __syncthreads();
        float o[4];
#pragma unroll
        for (int j = 0; j < 4; j++) {
            int c = c0 + j;
            int d = c & 63;
            int i2 = d & 31;
            float cs = g_cs[s * 32 + i2];
            float sn = g_sn[s * 32 + i2];
            float rot = (d < 32) ? -buf[c + 32] : buf[c - 32];
            o[j] = buf[c] * cs + rot * sn;
        }
        ((float4*)rowp)[tid] = make_float4(o[0], o[1], o[2], o[3]);
        __syncthreads();   // buf/rs reuse in next pass
    }
}

// ---------------- SIMT fp32 GEMM: C[M,N] = A[M,K] @ B[K,N], 128x128x8, 8x8/thread ----------------
template<int NN, int KK>
__global__ void __launch_bounds__(256) gemm_kernel(
    const float* __restrict__ A, const float* __restrict__ B, float* __restrict__ C) {
    __shared__ float As[8][128];
    __shared__ float Bs[8][128];
    int tid = threadIdx.x;
    int brow = blockIdx.y * 128;
    int bcol = blockIdx.x * 128;
    int a_row = tid >> 1, a_col = (tid & 1) << 2;
    int b_row = tid >> 5, b_col = (tid & 31) << 2;
    int ty = tid >> 4, tx = tid & 15;
    float acc[8][8] = {};
    const float* Ap = A + (size_t)(brow + a_row) * KK + a_col;
    const float* Bp = B + (size_t)b_row * NN + bcol + b_col;
    for (int k0 = 0; k0 < KK; k0 += 8) {
        float4 av = *(const float4*)(Ap + k0);
        float4 bv = *(const float4*)(Bp + (size_t)k0 * NN);
        __syncthreads();
        As[a_col + 0][a_row] = av.x;
        As[a_col + 1][a_row] = av.y;
        As[a_col + 2][a_row] = av.z;
        As[a_col + 3][a_row] = av.w;
        *(float4*)&Bs[b_row][b_col] = bv;
        __syncthreads();
#pragma unroll
        for (int kk = 0; kk < 8; kk++) {
            float ar[8], br[8];
#pragma unroll
            for (int i = 0; i < 8; i++) ar[i] = As[kk][ty * 8 + i];
#pragma unroll
            for (int j = 0; j < 8; j++) br[j] = Bs[kk][tx * 8 + j];
#pragma unroll
            for (int i = 0; i < 8; i++)
#pragma unroll
                for (int j = 0; j < 8; j++)
                    acc[i][j] = fmaf(ar[i], br[j], acc[i][j]);
        }
    }
#pragma unroll
    for (int i = 0; i < 8; i++) {
        float* cp = C + (size_t)(brow + ty * 8 + i) * NN + bcol + tx * 8;
#pragma unroll
        for (int j = 0; j < 8; j += 4)
            *(float4*)(cp + j) = make_float4(acc[i][j], acc[i][j+1], acc[i][j+2], acc[i][j+3]);
    }
}

// ---------------- flash attention, 64x64 tiles, online softmax, tile skipping ----------------
struct AttnSmem {
    float Qs[64][65];
    float Ks[64][65];
    float Vs[64][65];
    float Ss[64][65];
    float mrow[64], lrow[64], alpha[64];
    int   sidq[64], sidk[64];
};

__global__ void __launch_bounds__(256) attn_kernel() {
    extern __shared__ char smem_raw[];
    AttnSmem& sm = *(AttnSmem*)smem_raw;
    int tid = threadIdx.x;
    int tx = tid & 15, ty = tid >> 4;
    int q0 = blockIdx.x * 64;
    int bh = blockIdx.y;
    int b = bh >> 4, h = bh & 15;

    const float* qbase = g_qkv + ((size_t)(b * LL + q0)) * 3 * DDM + h * 64;
#pragma unroll
    for (int it = 0; it < 4; it++) {
        int idx = tid + it * 256;
        int r = idx >> 4, c4 = idx & 15;
        float4 v = *(const float4*)(qbase + (size_t)r * 3 * DDM + c4 * 4);
        sm.Qs[r][c4*4+0] = v.x; sm.Qs[r][c4*4+1] = v.y;
        sm.Qs[r][c4*4+2] = v.z; sm.Qs[r][c4*4+3] = v.w;
    }
    if (tid < 64) {
        sm.sidq[tid] = g_sid[b * LL + q0 + tid];
        sm.mrow[tid] = -INFINITY;
        sm.lrow[tid] = 0.f;
    }
    float O[4][4] = {};

    for (int kt = 0; kt < LL / 64; kt++) {
        if (tid >= 64 && tid < 128)
            sm.sidk[tid - 64] = g_sid[b * LL + kt * 64 + (tid - 64)];
        __syncthreads();
        // sequence_id is sorted along L -> tile ranges; skip fully-masked tiles (block-uniform)
        bool active = !(sm.sidk[63] < sm.sidq[0] || sm.sidk[0] > sm.sidq[63]);
        if (active) {
            const float* kb = g_qkv + ((size_t)(b * LL + kt * 64)) * 3 * DDM + DDM + h * 64;
            const float* vb = kb + DDM;
#pragma unroll
            for (int it = 0; it < 4; it++) {
                int idx = tid + it * 256;
                int r = idx >> 4, c4 = idx & 15;
                float4 kv = *(const float4*)(kb + (size_t)r * 3 * DDM + c4 * 4);
                sm.Ks[r][c4*4+0] = kv.x; sm.Ks[r][c4*4+1] = kv.y;
                sm.Ks[r][c4*4+2] = kv.z; sm.Ks[r][c4*4+3] = kv.w;
                float4 vv = *(const float4*)(vb + (size_t)r * 3 * DDM + c4 * 4);
                sm.Vs[r][c4*4+0] = vv.x; sm.Vs[r][c4*4+1] = vv.y;
                sm.Vs[r][c4*4+2] = vv.z; sm.Vs[r][c4*4+3] = vv.w;
            }
            __syncthreads();

            // S = Q @ K^T (4x4 per thread)
            float sacc[4][4] = {};
#pragma unroll
            for (int d = 0; d < 64; d++) {
                float qa[4], ka[4];
#pragma unroll
                for (int i = 0; i < 4; i++) qa[i] = sm.Qs[ty*4+i][d];
#pragma unroll
                for (int j = 0; j < 4; j++) ka[j] = sm.Ks[tx*4+j][d];
#pragma unroll
                for (int i = 0; i < 4; i++)
#pragma unroll
                    for (int j = 0; j < 4; j++)
                        sacc[i][j] = fmaf(qa[i], ka[j], sacc[i][j]);
            }
#pragma unroll
            for (int i = 0; i < 4; i++)
#pragma unroll
                for (int j = 0; j < 4; j++) {
                    int r = ty*4+i, c = tx*4+j;
                    float sv = sacc[i][j] * 0.125f;
                    if (sm.sidq[r] != sm.sidk[c]) sv = -1e30f;
                    sm.Ss[r][c] = sv;
                }
            __syncthreads();

            // online softmax: 4 threads per row
            {
                int r = tid >> 2, sub = tid & 3;
                float mloc = -INFINITY;
#pragma unroll
                for (int c = sub; c < 64; c += 4) mloc = fmaxf(mloc, sm.Ss[r][c]);
                mloc = fmaxf(mloc, __shfl_xor_sync(0xffffffffu, mloc, 1));
                mloc = fmaxf(mloc, __shfl_xor_sync(0xffffffffu, mloc, 2));
                float mold = sm.mrow[r];
                float mnew = fmaxf(mold, mloc);
                float ls = 0.f;
#pragma unroll
                for (int c = sub; c < 64; c += 4) {
                    float p = __expf(sm.Ss[r][c] - mnew);
                    sm.Ss[r][c] = p;
                    ls += p;
                }
                ls += __shfl_xor_sync(0xffffffffu, ls, 1);
                ls += __shfl_xor_sync(0xffffffffu, ls, 2);
                if (sub == 0) {
                    float a = __expf(mold - mnew);
                    sm.alpha[r] = a;
                    sm.lrow[r] = sm.lrow[r] * a + ls;
                    sm.mrow[r] = mnew;
                }
            }
            __syncthreads();

            // O = O*alpha + P @ V
#pragma unroll
            for (int i = 0; i < 4; i++) {
                float a = sm.alpha[ty*4+i];
#pragma unroll
                for (int j = 0; j < 4; j++) O[i][j] *= a;
            }
#pragma unroll
            for (int c = 0; c < 64; c++) {
                float pv[4], vv[4];
#pragma unroll
                for (int i = 0; i < 4; i++) pv[i] = sm.Ss[ty*4+i][c];
#pragma unroll
                for (int j = 0; j < 4; j++) vv[j] = sm.Vs[c][tx*4+j];
#pragma unroll
                for (int i = 0; i < 4; i++)
#pragma unroll
                    for (int j = 0; j < 4; j++)
                        O[i][j] = fmaf(pv[i], vv[j], O[i][j]);
            }
        }
        __syncthreads();   // protect sidk/tiles for next iteration
    }

#pragma unroll
    for (int i = 0; i < 4; i++) {
        int r = ty * 4 + i;
        float il = 1.0f / sm.lrow[r];
        float4 o = make_float4(O[i][0]*il, O[i][1]*il, O[i][2]*il, O[i][3]*il);
        *(float4*)(g_ctx + ((size_t)(b * LL + q0 + r)) * DDM + h * 64 + tx * 4) = o;
    }
}

// ---------------- launch ----------------
extern "C" void kernel_launch(void* const* d_in, const int* in_sizes, int n_in,
                              void* d_out, int out_size) {
    (void)in_sizes; (void)n_in; (void)out_size;
    const float* x      = (const float*)d_in[0];
    const void*  seq    = d_in[1];                 // int32 or int64 — sniffed on device
    const float* ln_w   = (const float*)d_in[2];
    const float* ln_b   = (const float*)d_in[3];
    const float* w_qkv  = (const float*)d_in[4];
    const float* q_ln_w = (const float*)d_in[5];
    const float* k_ln_w = (const float*)d_in[6];
    const float* w_out  = (const float*)d_in[7];
    float* out = (float*)d_out;

    float *p_ln, *p_qkv, *p_ctx;
    cudaGetSymbolAddress((void**)&p_ln,  g_ln);
    cudaGetSymbolAddress((void**)&p_qkv, g_qkv);
    cudaGetSymbolAddress((void**)&p_ctx, g_ctx);

    int attn_smem = (int)sizeof(AttnSmem);
    cudaFuncSetAttribute(attn_kernel, cudaFuncAttributeMaxDynamicSharedMemorySize, attn_smem);

    sid_norm_kernel<<<(NT + 255) / 256, 256>>>(seq);
    rope_table_kernel<<<(LL * 32 + 255) / 256, 256>>>();
    ln_kernel<<<NT, 256>>>(x, ln_w, ln_b);
    gemm_kernel<3 * DDM, DDM><<<dim3(3 * DDM / 128, NT / 128), 256>>>(p_ln, w_qkv, p_qkv);
    qkln_rope_kernel<<<NT, 256>>>(q_ln_w, k_ln_w);
    attn_kernel<<<dim3(LL / 64, BB * HH), 256, attn_smem>>>();
    gemm_kernel<DDM, DDM><<<dim3(DDM / 128, NT / 128), 256>>>(p_ctx, w_out, out);
}

// round 4
// speedup vs baseline: 1.5390x; 1.5390x over previous
#include <cuda_runtime.h>
#include <cuda_bf16.h>
#include <math.h>
#include <cstdint>

#define BB 4
#define LL 2048
#define DDM 1024
#define HH 16
#define NT (BB*LL)   // 8192 tokens

// ---------------- scratch (device globals: allocation-free rule) ----------------
__device__ float          g_qkv[(size_t)NT * 3 * DDM];      // 96 MB fp32
__device__ __nv_bfloat16  g_x_hi[(size_t)NT * DDM];         // LN output split
__device__ __nv_bfloat16  g_x_lo[(size_t)NT * DDM];
__device__ __nv_bfloat16  g_ctx_hi[(size_t)NT * DDM];       // attention output split
__device__ __nv_bfloat16  g_ctx_lo[(size_t)NT * DDM];
__device__ __nv_bfloat16  g_wqkv_hi[(size_t)3 * DDM * DDM]; // w_qkv^T [3072][1024]
__device__ __nv_bfloat16  g_wqkv_lo[(size_t)3 * DDM * DDM];
__device__ __nv_bfloat16  g_wout_hi[(size_t)DDM * DDM];     // w_out^T [1024][1024]
__device__ __nv_bfloat16  g_wout_lo[(size_t)DDM * DDM];
__device__ float g_cs[LL * 32];
__device__ float g_sn[LL * 32];
__device__ int   g_sid[NT];

// ---------------- sequence_id dtype sniff + normalize ----------------
__global__ void sid_norm_kernel(const void* __restrict__ seqraw) {
    const int* w = (const int*)seqraw;
    bool is64 = (w[2*1000+1] == 0) && (w[2*1500+1] == 0) && (w[2*2047+1] == 0);
    int i = blockIdx.x * blockDim.x + threadIdx.x;
    if (i < NT) g_sid[i] = is64 ? w[2*i] : w[i];
}

// ---------------- rope tables (fp64 for angle accuracy) ----------------
__global__ void rope_table_kernel() {
    int idx = blockIdx.x * blockDim.x + threadIdx.x;
    if (idx >= LL * 32) return;
    int s = idx >> 5, i = idx & 31;
    double ang = (double)s * pow(10000.0, -(double)i / 32.0);
    g_cs[idx] = (float)cos(ang);
    g_sn[idx] = (float)sin(ang);
}

// ---------------- weight prep: transpose [K][N] -> [N][K] + bf16 split ----------------
__global__ void __launch_bounds__(256) wprep_kernel(
    const float* __restrict__ w, __nv_bfloat16* __restrict__ thi,
    __nv_bfloat16* __restrict__ tlo, int N) {
    __shared__ float t[32][33];
    int n0 = blockIdx.x * 32, k0 = blockIdx.y * 32;
    int tx = threadIdx.x & 31, ty = threadIdx.x >> 5;
#pragma unroll
    for (int i = 0; i < 4; i++)
        t[ty + 8*i][tx] = w[(size_t)(k0 + ty + 8*i) * N + n0 + tx];
    __syncthreads();
#pragma unroll
    for (int i = 0; i < 4; i++) {
        float v = t[tx][ty + 8*i];
        __nv_bfloat16 h = __float2bfloat16(v);
        __nv_bfloat16 l = __float2bfloat16(v - __bfloat162float(h));
        size_t o = (size_t)(n0 + ty + 8*i) * 1024 + k0 + tx;
        thi[o] = h; tlo[o] = l;
    }
}

// ---------------- input LayerNorm -> bf16 hi/lo split ----------------
__global__ void __launch_bounds__(256) ln_kernel(
    const float* __restrict__ x, const float* __restrict__ w, const float* __restrict__ b) {
    int row = blockIdx.x;
    int tid = threadIdx.x;
    float4 v = ((const float4*)(x + (size_t)row * DDM))[tid];
    float s  = v.x + v.y + v.z + v.w;
    float ss = v.x*v.x + v.y*v.y + v.z*v.z + v.w*v.w;
    __shared__ float rs[8], rss[8];
#pragma unroll
    for (int o = 16; o; o >>= 1) {
        s  += __shfl_xor_sync(0xffffffffu, s,  o);
        ss += __shfl_xor_sync(0xffffffffu, ss, o);
    }
    if ((tid & 31) == 0) { rs[tid >> 5] = s; rss[tid >> 5] = ss; }
    __syncthreads();
    if (tid == 0) {
        float a = 0.f, c = 0.f;
#pragma unroll
        for (int i = 0; i < 8; i++) { a += rs[i]; c += rss[i]; }
        rs[0] = a; rss[0] = c;
    }
    __syncthreads();
    float mean = rs[0] * (1.0f / DDM);
    float var  = rss[0] * (1.0f / DDM) - mean * mean;
    float rstd = rsqrtf(var + 1e-5f);
    float4 wv = ((const float4*)w)[tid];
    float4 bv = ((const float4*)b)[tid];
    float o[4];
    o[0] = (v.x - mean) * rstd * wv.x + bv.x;
    o[1] = (v.y - mean) * rstd * wv.y + bv.y;
    o[2] = (v.z - mean) * rstd * wv.z + bv.z;
    o[3] = (v.w - mean) * rstd * wv.w + bv.w;
    size_t base = (size_t)row * DDM + tid * 4;
    __nv_bfloat16 h[4], l[4];
#pragma unroll
    for (int j = 0; j < 4; j++) {
        h[j] = __float2bfloat16(o[j]);
        l[j] = __float2bfloat16(o[j] - __bfloat162float(h[j]));
    }
    *(uint2*)(g_x_hi + base) = *(uint2*)h;
    *(uint2*)(g_x_lo + base) = *(uint2*)l;
}

// ---------------- mma.sync bf16 helper ----------------
__device__ __forceinline__ void mma_bf16(float* d, const uint32_t* a, const uint32_t* b) {
    asm volatile(
        "mma.sync.aligned.m16n8k16.row.col.f32.bf16.bf16.f32 "
        "{%0,%1,%2,%3}, {%4,%5,%6,%7}, {%8,%9}, {%0,%1,%2,%3};"
        : "+f"(d[0]), "+f"(d[1]), "+f"(d[2]), "+f"(d[3])
        : "r"(a[0]), "r"(a[1]), "r"(a[2]), "r"(a[3]), "r"(b[0]), "r"(b[1]));
}

// ---------------- tensor GEMM via mma.sync: C[M,NN] = A[M,1024] @ B^T ----------------
// A: [M][1024] bf16 hi/lo row-major. B: [NN][1024] bf16 hi/lo row-major (= B^T).
// CTA tile 128x128, 8 warps as 2(M) x 4(N), warp tile 64x32.
// 3-term split: Ah*Bh + Ah*Bl + Al*Bh, fp32 accumulate.
#define SPAD 20   // smem row pitch in b32 words (40 bf16): conflict-free permutation
template<int NN>
__global__ void __launch_bounds__(256) gemm_mma_kernel(
    const __nv_bfloat16* __restrict__ Ahi, const __nv_bfloat16* __restrict__ Alo,
    const __nv_bfloat16* __restrict__ Bhi, const __nv_bfloat16* __restrict__ Blo,
    float* __restrict__ C) {
    __shared__ uint32_t sAh[128 * SPAD], sAl[128 * SPAD];
    __shared__ uint32_t sBh[128 * SPAD], sBl[128 * SPAD];
    int tid = threadIdx.x, lane = tid & 31, wid = tid >> 5;
    int m0 = blockIdx.y * 128, n0 = blockIdx.x * 128;
    int wm = (wid & 1) * 64, wn = (wid >> 1) * 32;
    int g = lane >> 2, q = lane & 3;          // fragment group / quad
    int lrow = tid >> 2, lu = tid & 3;        // staging: 4 uint4 per 32-col row

    float acc[4][4][4] = {};                   // [mfrag][nfrag][reg]

    for (int kc = 0; kc < 32; kc++) {
        __syncthreads();
#pragma unroll
        for (int h = 0; h < 2; h++) {
            int row = lrow + h * 64;
            size_t gA = (size_t)(m0 + row) * 1024 + kc * 32 + lu * 8;
            size_t gB = (size_t)(n0 + row) * 1024 + kc * 32 + lu * 8;
            *(uint4*)&sAh[row * SPAD + lu * 4] = *(const uint4*)(Ahi + gA);
            *(uint4*)&sAl[row * SPAD + lu * 4] = *(const uint4*)(Alo + gA);
            *(uint4*)&sBh[row * SPAD + lu * 4] = *(const uint4*)(Bhi + gB);
            *(uint4*)&sBl[row * SPAD + lu * 4] = *(const uint4*)(Blo + gB);
        }
        __syncthreads();
#pragma unroll
        for (int ks = 0; ks < 2; ks++) {
            int kw = ks * 8 + q;
            uint32_t ah[4][4], al[4][4], bh[4][2], bl[4][2];
#pragma unroll
            for (int mf = 0; mf < 4; mf++) {
                int m = wm + mf * 16 + g;
                ah[mf][0] = sAh[m * SPAD + kw];
                ah[mf][1] = sAh[(m + 8) * SPAD + kw];
                ah[mf][2] = sAh[m * SPAD + kw + 4];
                ah[mf][3] = sAh[(m + 8) * SPAD + kw + 4];
                al[mf][0] = sAl[m * SPAD + kw];
                al[mf][1] = sAl[(m + 8) * SPAD + kw];
                al[mf][2] = sAl[m * SPAD + kw + 4];
                al[mf][3] = sAl[(m + 8) * SPAD + kw + 4];
            }
#pragma unroll
            for (int nf = 0; nf < 4; nf++) {
                int n = wn + nf * 8 + g;
                bh[nf][0] = sBh[n * SPAD + kw];
                bh[nf][1] = sBh[n * SPAD + kw + 4];
                bl[nf][0] = sBl[n * SPAD + kw];
                bl[nf][1] = sBl[n * SPAD + kw + 4];
            }
#pragma unroll
            for (int mf = 0; mf < 4; mf++)
#pragma unroll
                for (int nf = 0; nf < 4; nf++) {
                    mma_bf16(acc[mf][nf], ah[mf], bh[nf]);
                    mma_bf16(acc[mf][nf], ah[mf], bl[nf]);
                    mma_bf16(acc[mf][nf], al[mf], bh[nf]);
                }
        }
    }
#pragma unroll
    for (int mf = 0; mf < 4; mf++)
#pragma unroll
        for (int nf = 0; nf < 4; nf++) {
            int m = m0 + wm + mf * 16 + g;
            int n = n0 + wn + nf * 8 + q * 2;
            *(float2*)&C[(size_t)m * NN + n]       = make_float2(acc[mf][nf][0], acc[mf][nf][1]);
            *(float2*)&C[(size_t)(m + 8) * NN + n] = make_float2(acc[mf][nf][2], acc[mf][nf][3]);
        }
}

// ---------------- QK LayerNorm (scale-only) + RoPE, in place on g_qkv ----------------
__global__ void __launch_bounds__(256) qkln_rope_kernel(
    const float* __restrict__ qw, const float* __restrict__ kw) {
    int token = blockIdx.x;
    int tid = threadIdx.x;
    int s = token & (LL - 1);
    __shared__ float buf[DDM];
    __shared__ float rs[8], rss[8];
    for (int pass = 0; pass < 2; pass++) {
        float* rowp = g_qkv + (size_t)token * 3 * DDM + pass * DDM;
        const float* w = pass ? kw : qw;
        float4 v = ((const float4*)rowp)[tid];
        float sm = v.x + v.y + v.z + v.w;
        float sq = v.x*v.x + v.y*v.y + v.z*v.z + v.w*v.w;
#pragma unroll
        for (int o = 16; o; o >>= 1) {
            sm += __shfl_xor_sync(0xffffffffu, sm, o);
            sq += __shfl_xor_sync(0xffffffffu, sq, o);
        }
        if ((tid & 31) == 0) { rs[tid >> 5] = sm; rss[tid >> 5] = sq; }
        __syncthreads();
        if (tid == 0) {
            float a = 0.f, c = 0.f;
#pragma unroll
            for (int i = 0; i < 8; i++) { a += rs[i]; c += rss[i]; }
            rs[0] = a; rss[0] = c;
        }
        __syncthreads();
        float mean = rs[0] * (1.0f / DDM);
        float var  = rss[0] * (1.0f / DDM) - mean * mean;
        float rstd = rsqrtf(var + 1e-5f);
        float4 wv = ((const float4*)w)[tid];
        int c0 = tid * 4;
        buf[c0 + 0] = (v.x - mean) * rstd * wv.x;
        buf[c0 + 1] = (v.y - mean) * rstd * wv.y;
        buf[c0 + 2] = (v.z - mean) * rstd * wv.z;
        buf[c0 + 3] = (v.w - mean) * rstd * wv.w;
        __syncthreads();
        float o[4];
#pragma unroll
        for (int j = 0; j < 4; j++) {
            int c = c0 + j;
            int d = c & 63;
            int i2 = d & 31;
            float cs = g_cs[s * 32 + i2];
            float sn = g_sn[s * 32 + i2];
            float rot = (d < 32) ? -buf[c + 32] : buf[c - 32];
            o[j] = buf[c] * cs + rot * sn;
        }
        ((float4*)rowp)[tid] = make_float4(o[0], o[1], o[2], o[3]);
        __syncthreads();
    }
}

// ---------------- flash attention, 64x64 tiles, online softmax, tile skipping ----------------
struct AttnSmem {
    float Qs[64][65];
    float Ks[64][65];
    float Vs[64][65];
    float Ss[64][65];
    float mrow[64], lrow[64], alpha[64];
    int   sidq[64], sidk[64];
};

__global__ void __launch_bounds__(256) attn_kernel() {
    extern __shared__ char smem_raw[];
    AttnSmem& sm = *(AttnSmem*)smem_raw;
    int tid = threadIdx.x;
    int tx = tid & 15, ty = tid >> 4;
    int q0 = blockIdx.x * 64;
    int bh = blockIdx.y;
    int b = bh >> 4, h = bh & 15;

    const float* qbase = g_qkv + ((size_t)(b * LL + q0)) * 3 * DDM + h * 64;
#pragma unroll
    for (int it = 0; it < 4; it++) {
        int idx = tid + it * 256;
        int r = idx >> 4, c4 = idx & 15;
        float4 v = *(const float4*)(qbase + (size_t)r * 3 * DDM + c4 * 4);
        sm.Qs[r][c4*4+0] = v.x; sm.Qs[r][c4*4+1] = v.y;
        sm.Qs[r][c4*4+2] = v.z; sm.Qs[r][c4*4+3] = v.w;
    }
    if (tid < 64) {
        sm.sidq[tid] = g_sid[b * LL + q0 + tid];
        sm.mrow[tid] = -INFINITY;
        sm.lrow[tid] = 0.f;
    }
    float O[4][4] = {};

    for (int kt = 0; kt < LL / 64; kt++) {
        if (tid >= 64 && tid < 128)
            sm.sidk[tid - 64] = g_sid[b * LL + kt * 64 + (tid - 64)];
        __syncthreads();
        bool active = !(sm.sidk[63] < sm.sidq[0] || sm.sidk[0] > sm.sidq[63]);
        if (active) {
            const float* kb = g_qkv + ((size_t)(b * LL + kt * 64)) * 3 * DDM + DDM + h * 64;
            const float* vb = kb + DDM;
#pragma unroll
            for (int it = 0; it < 4; it++) {
                int idx = tid + it * 256;
                int r = idx >> 4, c4 = idx & 15;
                float4 kv = *(const float4*)(kb + (size_t)r * 3 * DDM + c4 * 4);
                sm.Ks[r][c4*4+0] = kv.x; sm.Ks[r][c4*4+1] = kv.y;
                sm.Ks[r][c4*4+2] = kv.z; sm.Ks[r][c4*4+3] = kv.w;
                float4 vv = *(const float4*)(vb + (size_t)r * 3 * DDM + c4 * 4);
                sm.Vs[r][c4*4+0] = vv.x; sm.Vs[r][c4*4+1] = vv.y;
                sm.Vs[r][c4*4+2] = vv.z; sm.Vs[r][c4*4+3] = vv.w;
            }
            __syncthreads();

            float sacc[4][4] = {};
#pragma unroll
            for (int d = 0; d < 64; d++) {
                float qa[4], ka[4];
#pragma unroll
                for (int i = 0; i < 4; i++) qa[i] = sm.Qs[ty*4+i][d];
#pragma unroll
                for (int j = 0; j < 4; j++) ka[j] = sm.Ks[tx*4+j][d];
#pragma unroll
                for (int i = 0; i < 4; i++)
#pragma unroll
                    for (int j = 0; j < 4; j++)
                        sacc[i][j] = fmaf(qa[i], ka[j], sacc[i][j]);
            }
#pragma unroll
            for (int i = 0; i < 4; i++)
#pragma unroll
                for (int j = 0; j < 4; j++) {
                    int r = ty*4+i, c = tx*4+j;
                    float sv = sacc[i][j] * 0.125f;
                    if (sm.sidq[r] != sm.sidk[c]) sv = -1e30f;
                    sm.Ss[r][c] = sv;
                }
            __syncthreads();

            {
                int r = tid >> 2, sub = tid & 3;
                float mloc = -INFINITY;
#pragma unroll
                for (int c = sub; c < 64; c += 4) mloc = fmaxf(mloc, sm.Ss[r][c]);
                mloc = fmaxf(mloc, __shfl_xor_sync(0xffffffffu, mloc, 1));
                mloc = fmaxf(mloc, __shfl_xor_sync(0xffffffffu, mloc, 2));
                float mold = sm.mrow[r];
                float mnew = fmaxf(mold, mloc);
                float ls = 0.f;
#pragma unroll
                for (int c = sub; c < 64; c += 4) {
                    float p = __expf(sm.Ss[r][c] - mnew);
                    sm.Ss[r][c] = p;
                    ls += p;
                }
                ls += __shfl_xor_sync(0xffffffffu, ls, 1);
                ls += __shfl_xor_sync(0xffffffffu, ls, 2);
                if (sub == 0) {
                    float a = __expf(mold - mnew);
                    sm.alpha[r] = a;
                    sm.lrow[r] = sm.lrow[r] * a + ls;
                    sm.mrow[r] = mnew;
                }
            }
            __syncthreads();

#pragma unroll
            for (int i = 0; i < 4; i++) {
                float a = sm.alpha[ty*4+i];
#pragma unroll
                for (int j = 0; j < 4; j++) O[i][j] *= a;
            }
#pragma unroll
            for (int c = 0; c < 64; c++) {
                float pv[4], vv[4];
#pragma unroll
                for (int i = 0; i < 4; i++) pv[i] = sm.Ss[ty*4+i][c];
#pragma unroll
                for (int j = 0; j < 4; j++) vv[j] = sm.Vs[c][tx*4+j];
#pragma unroll
                for (int i = 0; i < 4; i++)
#pragma unroll
                    for (int j = 0; j < 4; j++)
                        O[i][j] = fmaf(pv[i], vv[j], O[i][j]);
            }
        }
        __syncthreads();
    }

    // epilogue: bf16 hi/lo split for the out-projection tensor GEMM
#pragma unroll
    for (int i = 0; i < 4; i++) {
        int r = ty * 4 + i;
        float il = 1.0f / sm.lrow[r];
        size_t base = ((size_t)(b * LL + q0 + r)) * DDM + h * 64 + tx * 4;
        __nv_bfloat16 hv[4], lv[4];
#pragma unroll
        for (int j = 0; j < 4; j++) {
            float o = O[i][j] * il;
            hv[j] = __float2bfloat16(o);
            lv[j] = __float2bfloat16(o - __bfloat162float(hv[j]));
        }
        *(uint2*)(g_ctx_hi + base) = *(uint2*)hv;
        *(uint2*)(g_ctx_lo + base) = *(uint2*)lv;
    }
}

// ---------------- launch ----------------
extern "C" void kernel_launch(void* const* d_in, const int* in_sizes, int n_in,
                              void* d_out, int out_size) {
    (void)in_sizes; (void)n_in; (void)out_size;
    const float* x      = (const float*)d_in[0];
    const void*  seq    = d_in[1];
    const float* ln_w   = (const float*)d_in[2];
    const float* ln_b   = (const float*)d_in[3];
    const float* w_qkv  = (const float*)d_in[4];
    const float* q_ln_w = (const float*)d_in[5];
    const float* k_ln_w = (const float*)d_in[6];
    const float* w_out  = (const float*)d_in[7];
    float* out = (float*)d_out;

    float* p_qkv;
    __nv_bfloat16 *p_xh, *p_xl, *p_ch, *p_cl, *p_wqh, *p_wql, *p_woh, *p_wol;
    cudaGetSymbolAddress((void**)&p_qkv, g_qkv);
    cudaGetSymbolAddress((void**)&p_xh,  g_x_hi);
    cudaGetSymbolAddress((void**)&p_xl,  g_x_lo);
    cudaGetSymbolAddress((void**)&p_ch,  g_ctx_hi);
    cudaGetSymbolAddress((void**)&p_cl,  g_ctx_lo);
    cudaGetSymbolAddress((void**)&p_wqh, g_wqkv_hi);
    cudaGetSymbolAddress((void**)&p_wql, g_wqkv_lo);
    cudaGetSymbolAddress((void**)&p_woh, g_wout_hi);
    cudaGetSymbolAddress((void**)&p_wol, g_wout_lo);

    int attn_smem = (int)sizeof(AttnSmem);
    cudaFuncSetAttribute(attn_kernel, cudaFuncAttributeMaxDynamicSharedMemorySize, attn_smem);

    sid_norm_kernel<<<(NT + 255) / 256, 256>>>(seq);
    rope_table_kernel<<<(LL * 32 + 255) / 256, 256>>>();
    wprep_kernel<<<dim3(3 * DDM / 32, DDM / 32), 256>>>(w_qkv, p_wqh, p_wql, 3 * DDM);
    wprep_kernel<<<dim3(DDM / 32, DDM / 32), 256>>>(w_out, p_woh, p_wol, DDM);
    ln_kernel<<<NT, 256>>>(x, ln_w, ln_b);
    gemm_mma_kernel<3 * DDM><<<dim3(3 * DDM / 128, NT / 128), 256>>>(p_xh, p_xl, p_wqh, p_wql, p_qkv);
    qkln_rope_kernel<<<NT, 256>>>(q_ln_w, k_ln_w);
    attn_kernel<<<dim3(LL / 64, BB * HH), 256, attn_smem>>>();
    gemm_mma_kernel<DDM><<<dim3(DDM / 128, NT / 128), 256>>>(p_ch, p_cl, p_woh, p_wol, out);
}

// round 5
// speedup vs baseline: 1.8443x; 1.1984x over previous
#include <cuda_runtime.h>
#include <cuda_bf16.h>
#include <math.h>
#include <cstdint>

#define BB 4
#define LL 2048
#define DDM 1024
#define HH 16
#define NT (BB*LL)   // 8192 tokens

// ---------------- scratch (device globals: allocation-free rule) ----------------
__device__ float          g_qkv[(size_t)NT * 3 * DDM];      // 96 MB fp32
__device__ __nv_bfloat16  g_x_hi[(size_t)NT * DDM];         // LN output split
__device__ __nv_bfloat16  g_x_lo[(size_t)NT * DDM];
__device__ __nv_bfloat16  g_ctx_hi[(size_t)NT * DDM];       // attention output split
__device__ __nv_bfloat16  g_ctx_lo[(size_t)NT * DDM];
__device__ __nv_bfloat16  g_wqkv_hi[(size_t)3 * DDM * DDM]; // w_qkv^T [3072][1024]
__device__ __nv_bfloat16  g_wqkv_lo[(size_t)3 * DDM * DDM];
__device__ __nv_bfloat16  g_wout_hi[(size_t)DDM * DDM];     // w_out^T [1024][1024]
__device__ __nv_bfloat16  g_wout_lo[(size_t)DDM * DDM];
__device__ float g_cs[LL * 32];
__device__ float g_sn[LL * 32];
__device__ int   g_sid[NT];

// ---------------- sequence_id dtype sniff + normalize ----------------
__global__ void sid_norm_kernel(const void* __restrict__ seqraw) {
    const int* w = (const int*)seqraw;
    bool is64 = (w[2*1000+1] == 0) && (w[2*1500+1] == 0) && (w[2*2047+1] == 0);
    int i = blockIdx.x * blockDim.x + threadIdx.x;
    if (i < NT) g_sid[i] = is64 ? w[2*i] : w[i];
}

// ---------------- rope tables (fp64 for angle accuracy) ----------------
__global__ void rope_table_kernel() {
    int idx = blockIdx.x * blockDim.x + threadIdx.x;
    if (idx >= LL * 32) return;
    int s = idx >> 5, i = idx & 31;
    double ang = (double)s * pow(10000.0, -(double)i / 32.0);
    g_cs[idx] = (float)cos(ang);
    g_sn[idx] = (float)sin(ang);
}

// ---------------- weight prep: transpose [K][N] -> [N][K] + bf16 split ----------------
__global__ void __launch_bounds__(256) wprep_kernel(
    const float* __restrict__ w, __nv_bfloat16* __restrict__ thi,
    __nv_bfloat16* __restrict__ tlo, int N) {
    __shared__ float t[32][33];
    int n0 = blockIdx.x * 32, k0 = blockIdx.y * 32;
    int tx = threadIdx.x & 31, ty = threadIdx.x >> 5;
#pragma unroll
    for (int i = 0; i < 4; i++)
        t[ty + 8*i][tx] = w[(size_t)(k0 + ty + 8*i) * N + n0 + tx];
    __syncthreads();
#pragma unroll
    for (int i = 0; i < 4; i++) {
        float v = t[tx][ty + 8*i];
        __nv_bfloat16 h = __float2bfloat16(v);
        __nv_bfloat16 l = __float2bfloat16(v - __bfloat162float(h));
        size_t o = (size_t)(n0 + ty + 8*i) * 1024 + k0 + tx;
        thi[o] = h; tlo[o] = l;
    }
}

// ---------------- input LayerNorm -> bf16 hi/lo split ----------------
__global__ void __launch_bounds__(256) ln_kernel(
    const float* __restrict__ x, const float* __restrict__ w, const float* __restrict__ b) {
    int row = blockIdx.x;
    int tid = threadIdx.x;
    float4 v = ((const float4*)(x + (size_t)row * DDM))[tid];
    float s  = v.x + v.y + v.z + v.w;
    float ss = v.x*v.x + v.y*v.y + v.z*v.z + v.w*v.w;
    __shared__ float rs[8], rss[8];
#pragma unroll
    for (int o = 16; o; o >>= 1) {
        s  += __shfl_xor_sync(0xffffffffu, s,  o);
        ss += __shfl_xor_sync(0xffffffffu, ss, o);
    }
    if ((tid & 31) == 0) { rs[tid >> 5] = s; rss[tid >> 5] = ss; }
    __syncthreads();
    if (tid == 0) {
        float a = 0.f, c = 0.f;
#pragma unroll
        for (int i = 0; i < 8; i++) { a += rs[i]; c += rss[i]; }
        rs[0] = a; rss[0] = c;
    }
    __syncthreads();
    float mean = rs[0] * (1.0f / DDM);
    float var  = rss[0] * (1.0f / DDM) - mean * mean;
    float rstd = rsqrtf(var + 1e-5f);
    float4 wv = ((const float4*)w)[tid];
    float4 bv = ((const float4*)b)[tid];
    float o[4];
    o[0] = (v.x - mean) * rstd * wv.x + bv.x;
    o[1] = (v.y - mean) * rstd * wv.y + bv.y;
    o[2] = (v.z - mean) * rstd * wv.z + bv.z;
    o[3] = (v.w - mean) * rstd * wv.w + bv.w;
    size_t base = (size_t)row * DDM + tid * 4;
    __nv_bfloat16 h[4], l[4];
#pragma unroll
    for (int j = 0; j < 4; j++) {
        h[j] = __float2bfloat16(o[j]);
        l[j] = __float2bfloat16(o[j] - __bfloat162float(h[j]));
    }
    *(uint2*)(g_x_hi + base) = *(uint2*)h;
    *(uint2*)(g_x_lo + base) = *(uint2*)l;
}

// ---------------- mma.sync bf16 helper ----------------
__device__ __forceinline__ void mma_bf16(float* d, const uint32_t* a, const uint32_t* b) {
    asm volatile(
        "mma.sync.aligned.m16n8k16.row.col.f32.bf16.bf16.f32 "
        "{%0,%1,%2,%3}, {%4,%5,%6,%7}, {%8,%9}, {%0,%1,%2,%3};"
        : "+f"(d[0]), "+f"(d[1]), "+f"(d[2]), "+f"(d[3])
        : "r"(a[0]), "r"(a[1]), "r"(a[2]), "r"(a[3]), "r"(b[0]), "r"(b[1]));
}

// ---------------- cp.async helpers ----------------
__device__ __forceinline__ uint32_t smem_u32(const void* p) {
    uint32_t a;
    asm("{ .reg .u64 t; cvta.to.shared.u64 t, %1; cvt.u32.u64 %0, t; }" : "=r"(a) : "l"(p));
    return a;
}
__device__ __forceinline__ void cp16(uint32_t dst, const void* src) {
    asm volatile("cp.async.cg.shared.global [%0], [%1], 16;" :: "r"(dst), "l"(src));
}
__device__ __forceinline__ void cp_commit() {
    asm volatile("cp.async.commit_group;" ::: "memory");
}
template<int N>
__device__ __forceinline__ void cp_wait() {
    asm volatile("cp.async.wait_group %0;" :: "n"(N) : "memory");
}

// ---------------- tensor GEMM via mma.sync + cp.async 2-stage pipeline ----------------
// C[M,NN] = A[M,1024] @ B^T.  A: [M][1024] bf16 hi/lo. B: [NN][1024] bf16 hi/lo (= B^T).
// CTA tile 128x128, 8 warps as 2(M) x 4(N), warp tile 64x32, K-chunk 32, 32 chunks.
// 3-term split: Ah*Bh + Ah*Bl + Al*Bh, fp32 accumulate.
#define SPAD 20                    // smem row pitch in b32 words (40 bf16)
#define ARRW (128 * SPAD)          // words per array  (2560)
#define STGW (4 * ARRW)            // words per stage  (10240)
#define GEMM_SMEM_BYTES (2 * STGW * 4)   // 81920
template<int NN>
__global__ void __launch_bounds__(256) gemm_mma_kernel(
    const __nv_bfloat16* __restrict__ Ahi, const __nv_bfloat16* __restrict__ Alo,
    const __nv_bfloat16* __restrict__ Bhi, const __nv_bfloat16* __restrict__ Blo,
    float* __restrict__ C) {
    extern __shared__ uint32_t sw[];
    const uint32_t sb = smem_u32(sw);
    int tid = threadIdx.x, lane = tid & 31, wid = tid >> 5;
    int m0 = blockIdx.y * 128, n0 = blockIdx.x * 128;
    int wm = (wid & 1) * 64, wn = (wid >> 1) * 32;
    int g = lane >> 2, q = lane & 3;          // fragment group / quad
    int lrow = tid >> 2, lu = tid & 3;        // staging: 4x16B per 32-col row

    float acc[4][4][4] = {};                   // [mfrag][nfrag][reg]

    // issue cp.asyncs for one K-chunk into one stage (8 x 16B per thread)
    auto load_chunk = [&](int kc, int st) {
        uint32_t base = sb + (uint32_t)st * (STGW * 4);
#pragma unroll
        for (int h = 0; h < 2; h++) {
            int row = lrow + h * 64;
            uint32_t so = (uint32_t)(row * SPAD + lu * 4) * 4;
            size_t gA = (size_t)(m0 + row) * 1024 + kc * 32 + lu * 8;
            size_t gB = (size_t)(n0 + row) * 1024 + kc * 32 + lu * 8;
            cp16(base + 0 * ARRW * 4 + so, Ahi + gA);
            cp16(base + 1 * ARRW * 4 + so, Alo + gA);
            cp16(base + 2 * ARRW * 4 + so, Bhi + gB);
            cp16(base + 3 * ARRW * 4 + so, Blo + gB);
        }
    };

    load_chunk(0, 0);
    cp_commit();

    for (int kc = 0; kc < 32; kc++) {
        int st = kc & 1;
        if (kc < 31) { load_chunk(kc + 1, st ^ 1); cp_commit(); cp_wait<1>(); }
        else         { cp_wait<0>(); }
        __syncthreads();
        const uint32_t* pAh = sw + st * STGW + 0 * ARRW;
        const uint32_t* pAl = sw + st * STGW + 1 * ARRW;
        const uint32_t* pBh = sw + st * STGW + 2 * ARRW;
        const uint32_t* pBl = sw + st * STGW + 3 * ARRW;
#pragma unroll
        for (int ks = 0; ks < 2; ks++) {
            int kw = ks * 8 + q;
            uint32_t ah[4][4], al[4][4], bh[4][2], bl[4][2];
#pragma unroll
            for (int mf = 0; mf < 4; mf++) {
                int m = wm + mf * 16 + g;
                ah[mf][0] = pAh[m * SPAD + kw];
                ah[mf][1] = pAh[(m + 8) * SPAD + kw];
                ah[mf][2] = pAh[m * SPAD + kw + 4];
                ah[mf][3] = pAh[(m + 8) * SPAD + kw + 4];
                al[mf][0] = pAl[m * SPAD + kw];
                al[mf][1] = pAl[(m + 8) * SPAD + kw];
                al[mf][2] = pAl[m * SPAD + kw + 4];
                al[mf][3] = pAl[(m + 8) * SPAD + kw + 4];
            }
#pragma unroll
            for (int nf = 0; nf < 4; nf++) {
                int n = wn + nf * 8 + g;
                bh[nf][0] = pBh[n * SPAD + kw];
                bh[nf][1] = pBh[n * SPAD + kw + 4];
                bl[nf][0] = pBl[n * SPAD + kw];
                bl[nf][1] = pBl[n * SPAD + kw + 4];
            }
#pragma unroll
            for (int mf = 0; mf < 4; mf++)
#pragma unroll
                for (int nf = 0; nf < 4; nf++) {
                    mma_bf16(acc[mf][nf], ah[mf], bh[nf]);
                    mma_bf16(acc[mf][nf], ah[mf], bl[nf]);
                    mma_bf16(acc[mf][nf], al[mf], bh[nf]);
                }
        }
        __syncthreads();   // all warps done with stage st before it is refilled
    }
#pragma unroll
    for (int mf = 0; mf < 4; mf++)
#pragma unroll
        for (int nf = 0; nf < 4; nf++) {
            int m = m0 + wm + mf * 16 + g;
            int n = n0 + wn + nf * 8 + q * 2;
            *(float2*)&C[(size_t)m * NN + n]       = make_float2(acc[mf][nf][0], acc[mf][nf][1]);
            *(float2*)&C[(size_t)(m + 8) * NN + n] = make_float2(acc[mf][nf][2], acc[mf][nf][3]);
        }
}

// ---------------- QK LayerNorm (scale-only) + RoPE, in place on g_qkv ----------------
__global__ void __launch_bounds__(256) qkln_rope_kernel(
    const float* __restrict__ qw, const float* __restrict__ kw) {
    int token = blockIdx.x;
    int tid = threadIdx.x;
    int s = token & (LL - 1);
    __shared__ float buf[DDM];
    __shared__ float rs[8], rss[8];
    for (int pass = 0; pass < 2; pass++) {
        float* rowp = g_qkv + (size_t)token * 3 * DDM + pass * DDM;
        const float* w = pass ? kw : qw;
        float4 v = ((const float4*)rowp)[tid];
        float sm = v.x + v.y + v.z + v.w;
        float sq = v.x*v.x + v.y*v.y + v.z*v.z + v.w*v.w;
#pragma unroll
        for (int o = 16; o; o >>= 1) {
            sm += __shfl_xor_sync(0xffffffffu, sm, o);
            sq += __shfl_xor_sync(0xffffffffu, sq, o);
        }
        if ((tid & 31) == 0) { rs[tid >> 5] = sm; rss[tid >> 5] = sq; }
        __syncthreads();
        if (tid == 0) {
            float a = 0.f, c = 0.f;
#pragma unroll
            for (int i = 0; i < 8; i++) { a += rs[i]; c += rss[i]; }
            rs[0] = a; rss[0] = c;
        }
        __syncthreads();
        float mean = rs[0] * (1.0f / DDM);
        float var  = rss[0] * (1.0f / DDM) - mean * mean;
        float rstd = rsqrtf(var + 1e-5f);
        float4 wv = ((const float4*)w)[tid];
        int c0 = tid * 4;
        buf[c0 + 0] = (v.x - mean) * rstd * wv.x;
        buf[c0 + 1] = (v.y - mean) * rstd * wv.y;
        buf[c0 + 2] = (v.z - mean) * rstd * wv.z;
        buf[c0 + 3] = (v.w - mean) * rstd * wv.w;
        __syncthreads();
        float o[4];
#pragma unroll
        for (int j = 0; j < 4; j++) {
            int c = c0 + j;
            int d = c & 63;
            int i2 = d & 31;
            float cs = g_cs[s * 32 + i2];
            float sn = g_sn[s * 32 + i2];
            float rot = (d < 32) ? -buf[c + 32] : buf[c - 32];
            o[j] = buf[c] * cs + rot * sn;
        }
        ((float4*)rowp)[tid] = make_float4(o[0], o[1], o[2], o[3]);
        __syncthreads();
    }
}

// ---------------- flash attention, 64x64 tiles, online softmax, tile skipping ----------------
struct AttnSmem {
    float Qs[64][65];
    float Ks[64][65];
    float Vs[64][65];
    float Ss[64][65];
    float mrow[64], lrow[64], alpha[64];
    int   sidq[64], sidk[64];
};

__global__ void __launch_bounds__(256) attn_kernel() {
    extern __shared__ char smem_raw[];
    AttnSmem& sm = *(AttnSmem*)smem_raw;
    int tid = threadIdx.x;
    int tx = tid & 15, ty = tid >> 4;
    int q0 = blockIdx.x * 64;
    int bh = blockIdx.y;
    int b = bh >> 4, h = bh & 15;

    const float* qbase = g_qkv + ((size_t)(b * LL + q0)) * 3 * DDM + h * 64;
#pragma unroll
    for (int it = 0; it < 4; it++) {
        int idx = tid + it * 256;
        int r = idx >> 4, c4 = idx & 15;
        float4 v = *(const float4*)(qbase + (size_t)r * 3 * DDM + c4 * 4);
        sm.Qs[r][c4*4+0] = v.x; sm.Qs[r][c4*4+1] = v.y;
        sm.Qs[r][c4*4+2] = v.z; sm.Qs[r][c4*4+3] = v.w;
    }
    if (tid < 64) {
        sm.sidq[tid] = g_sid[b * LL + q0 + tid];
        sm.mrow[tid] = -INFINITY;
        sm.lrow[tid] = 0.f;
    }
    float O[4][4] = {};

    for (int kt = 0; kt < LL / 64; kt++) {
        if (tid >= 64 && tid < 128)
            sm.sidk[tid - 64] = g_sid[b * LL + kt * 64 + (tid - 64)];
        __syncthreads();
        bool active = !(sm.sidk[63] < sm.sidq[0] || sm.sidk[0] > sm.sidq[63]);
        if (active) {
            const float* kb = g_qkv + ((size_t)(b * LL + kt * 64)) * 3 * DDM + DDM + h * 64;
            const float* vb = kb + DDM;
#pragma unroll
            for (int it = 0; it < 4; it++) {
                int idx = tid + it * 256;
                int r = idx >> 4, c4 = idx & 15;
                float4 kv = *(const float4*)(kb + (size_t)r * 3 * DDM + c4 * 4);
                sm.Ks[r][c4*4+0] = kv.x; sm.Ks[r][c4*4+1] = kv.y;
                sm.Ks[r][c4*4+2] = kv.z; sm.Ks[r][c4*4+3] = kv.w;
                float4 vv = *(const float4*)(vb + (size_t)r * 3 * DDM + c4 * 4);
                sm.Vs[r][c4*4+0] = vv.x; sm.Vs[r][c4*4+1] = vv.y;
                sm.Vs[r][c4*4+2] = vv.z; sm.Vs[r][c4*4+3] = vv.w;
            }
            __syncthreads();

            float sacc[4][4] = {};
#pragma unroll
            for (int d = 0; d < 64; d++) {
                float qa[4], ka[4];
#pragma unroll
                for (int i = 0; i < 4; i++) qa[i] = sm.Qs[ty*4+i][d];
#pragma unroll
                for (int j = 0; j < 4; j++) ka[j] = sm.Ks[tx*4+j][d];
#pragma unroll
                for (int i = 0; i < 4; i++)
#pragma unroll
                    for (int j = 0; j < 4; j++)
                        sacc[i][j] = fmaf(qa[i], ka[j], sacc[i][j]);
            }
#pragma unroll
            for (int i = 0; i < 4; i++)
#pragma unroll
                for (int j = 0; j < 4; j++) {
                    int r = ty*4+i, c = tx*4+j;
                    float sv = sacc[i][j] * 0.125f;
                    if (sm.sidq[r] != sm.sidk[c]) sv = -1e30f;
                    sm.Ss[r][c] = sv;
                }
            __syncthreads();

            {
                int r = tid >> 2, sub = tid & 3;
                float mloc = -INFINITY;
#pragma unroll
                for (int c = sub; c < 64; c += 4) mloc = fmaxf(mloc, sm.Ss[r][c]);
                mloc = fmaxf(mloc, __shfl_xor_sync(0xffffffffu, mloc, 1));
                mloc = fmaxf(mloc, __shfl_xor_sync(0xffffffffu, mloc, 2));
                float mold = sm.mrow[r];
                float mnew = fmaxf(mold, mloc);
                float ls = 0.f;
#pragma unroll
                for (int c = sub; c < 64; c += 4) {
                    float p = __expf(sm.Ss[r][c] - mnew);
                    sm.Ss[r][c] = p;
                    ls += p;
                }
                ls += __shfl_xor_sync(0xffffffffu, ls, 1);
                ls += __shfl_xor_sync(0xffffffffu, ls, 2);
                if (sub == 0) {
                    float a = __expf(mold - mnew);
                    sm.alpha[r] = a;
                    sm.lrow[r] = sm.lrow[r] * a + ls;
                    sm.mrow[r] = mnew;
                }
            }
            __syncthreads();

#pragma unroll
            for (int i = 0; i < 4; i++) {
                float a = sm.alpha[ty*4+i];
#pragma unroll
                for (int j = 0; j < 4; j++) O[i][j] *= a;
            }
#pragma unroll
            for (int c = 0; c < 64; c++) {
                float pv[4], vv[4];
#pragma unroll
                for (int i = 0; i < 4; i++) pv[i] = sm.Ss[ty*4+i][c];
#pragma unroll
                for (int j = 0; j < 4; j++) vv[j] = sm.Vs[c][tx*4+j];
#pragma unroll
                for (int i = 0; i < 4; i++)
#pragma unroll
                    for (int j = 0; j < 4; j++)
                        O[i][j] = fmaf(pv[i], vv[j], O[i][j]);
            }
        }
        __syncthreads();
    }

    // epilogue: bf16 hi/lo split for the out-projection tensor GEMM
#pragma unroll
    for (int i = 0; i < 4; i++) {
        int r = ty * 4 + i;
        float il = 1.0f / sm.lrow[r];
        size_t base = ((size_t)(b * LL + q0 + r)) * DDM + h * 64 + tx * 4;
        __nv_bfloat16 hv[4], lv[4];
#pragma unroll
        for (int j = 0; j < 4; j++) {
            float o = O[i][j] * il;
            hv[j] = __float2bfloat16(o);
            lv[j] = __float2bfloat16(o - __bfloat162float(hv[j]));
        }
        *(uint2*)(g_ctx_hi + base) = *(uint2*)hv;
        *(uint2*)(g_ctx_lo + base) = *(uint2*)lv;
    }
}

// ---------------- launch ----------------
extern "C" void kernel_launch(void* const* d_in, const int* in_sizes, int n_in,
                              void* d_out, int out_size) {
    (void)in_sizes; (void)n_in; (void)out_size;
    const float* x      = (const float*)d_in[0];
    const void*  seq    = d_in[1];
    const float* ln_w   = (const float*)d_in[2];
    const float* ln_b   = (const float*)d_in[3];
    const float* w_qkv  = (const float*)d_in[4];
    const float* q_ln_w = (const float*)d_in[5];
    const float* k_ln_w = (const float*)d_in[6];
    const float* w_out  = (const float*)d_in[7];
    float* out = (float*)d_out;

    float* p_qkv;
    __nv_bfloat16 *p_xh, *p_xl, *p_ch, *p_cl, *p_wqh, *p_wql, *p_woh, *p_wol;
    cudaGetSymbolAddress((void**)&p_qkv, g_qkv);
    cudaGetSymbolAddress((void**)&p_xh,  g_x_hi);
    cudaGetSymbolAddress((void**)&p_xl,  g_x_lo);
    cudaGetSymbolAddress((void**)&p_ch,  g_ctx_hi);
    cudaGetSymbolAddress((void**)&p_cl,  g_ctx_lo);
    cudaGetSymbolAddress((void**)&p_wqh, g_wqkv_hi);
    cudaGetSymbolAddress((void**)&p_wql, g_wqkv_lo);
    cudaGetSymbolAddress((void**)&p_woh, g_wout_hi);
    cudaGetSymbolAddress((void**)&p_wol, g_wout_lo);

    cudaFuncSetAttribute(gemm_mma_kernel<3 * DDM>, cudaFuncAttributeMaxDynamicSharedMemorySize, GEMM_SMEM_BYTES);
    cudaFuncSetAttribute(gemm_mma_kernel<DDM>, cudaFuncAttributeMaxDynamicSharedMemorySize, GEMM_SMEM_BYTES);
    int attn_smem = (int)sizeof(AttnSmem);
    cudaFuncSetAttribute(attn_kernel, cudaFuncAttributeMaxDynamicSharedMemorySize, attn_smem);

    sid_norm_kernel<<<(NT + 255) / 256, 256>>>(seq);
    rope_table_kernel<<<(LL * 32 + 255) / 256, 256>>>();
    wprep_kernel<<<dim3(3 * DDM / 32, DDM / 32), 256>>>(w_qkv, p_wqh, p_wql, 3 * DDM);
    wprep_kernel<<<dim3(DDM / 32, DDM / 32), 256>>>(w_out, p_woh, p_wol, DDM);
    ln_kernel<<<NT, 256>>>(x, ln_w, ln_b);
    gemm_mma_kernel<3 * DDM><<<dim3(3 * DDM / 128, NT / 128), 256, GEMM_SMEM_BYTES>>>(p_xh, p_xl, p_wqh, p_wql, p_qkv);
    qkln_rope_kernel<<<NT, 256>>>(q_ln_w, k_ln_w);
    attn_kernel<<<dim3(LL / 64, BB * HH), 256, attn_smem>>>();
    gemm_mma_kernel<DDM><<<dim3(DDM / 128, NT / 128), 256, GEMM_SMEM_BYTES>>>(p_ch, p_cl, p_woh, p_wol, out);
}

// round 6
// speedup vs baseline: 2.1598x; 1.1710x over previous
#include <cuda_runtime.h>
#include <cuda_bf16.h>
#include <math.h>
#include <cstdint>

#define BB 4
#define LL 2048
#define DDM 1024
#define HH 16
#define NT (BB*LL)   // 8192 tokens

// ---------------- scratch (device globals: allocation-free rule) ----------------
__device__ float          g_qkv[(size_t)NT * 3 * DDM];      // 96 MB fp32
__device__ __nv_bfloat16  g_x_hi[(size_t)NT * DDM];         // LN output split
__device__ __nv_bfloat16  g_x_lo[(size_t)NT * DDM];
__device__ __nv_bfloat16  g_ctx_hi[(size_t)NT * DDM];       // attention output split
__device__ __nv_bfloat16  g_ctx_lo[(size_t)NT * DDM];
__device__ __nv_bfloat16  g_wqkv_hi[(size_t)3 * DDM * DDM]; // w_qkv^T [3072][1024]
__device__ __nv_bfloat16  g_wqkv_lo[(size_t)3 * DDM * DDM];
__device__ __nv_bfloat16  g_wout_hi[(size_t)DDM * DDM];     // w_out^T [1024][1024]
__device__ __nv_bfloat16  g_wout_lo[(size_t)DDM * DDM];
// head-major attention operands [b,h,l,64] (q,k) and [b,h,dh,l] (vT)
__device__ __nv_bfloat16  g_q_hi[(size_t)NT * 64 * HH];
__device__ __nv_bfloat16  g_q_lo[(size_t)NT * 64 * HH];
__device__ __nv_bfloat16  g_k_hi[(size_t)NT * 64 * HH];
__device__ __nv_bfloat16  g_k_lo[(size_t)NT * 64 * HH];
__device__ __nv_bfloat16  g_vT_hi[(size_t)NT * 64 * HH];
__device__ __nv_bfloat16  g_vT_lo[(size_t)NT * 64 * HH];
__device__ float g_cs[LL * 32];
__device__ float g_sn[LL * 32];
__device__ int   g_sid[NT];

// ---------------- sequence_id dtype sniff + normalize ----------------
__global__ void sid_norm_kernel(const void* __restrict__ seqraw) {
    const int* w = (const int*)seqraw;
    bool is64 = (w[2*1000+1] == 0) && (w[2*1500+1] == 0) && (w[2*2047+1] == 0);
    int i = blockIdx.x * blockDim.x + threadIdx.x;
    if (i < NT) g_sid[i] = is64 ? w[2*i] : w[i];
}

// ---------------- rope tables (fp64 for angle accuracy) ----------------
__global__ void rope_table_kernel() {
    int idx = blockIdx.x * blockDim.x + threadIdx.x;
    if (idx >= LL * 32) return;
    int s = idx >> 5, i = idx & 31;
    double ang = (double)s * pow(10000.0, -(double)i / 32.0);
    g_cs[idx] = (float)cos(ang);
    g_sn[idx] = (float)sin(ang);
}

// ---------------- helpers ----------------
__device__ __forceinline__ uint32_t bf16pack(float a, float b) {
    __nv_bfloat16 ha = __float2bfloat16(a), hb = __float2bfloat16(b);
    uint32_t r = ((uint32_t)*(uint16_t*)&hb << 16) | (uint32_t)*(uint16_t*)&ha;
    return r;
}
__device__ __forceinline__ void mma_bf16(float* d, const uint32_t* a, const uint32_t* b) {
    asm volatile(
        "mma.sync.aligned.m16n8k16.row.col.f32.bf16.bf16.f32 "
        "{%0,%1,%2,%3}, {%4,%5,%6,%7}, {%8,%9}, {%0,%1,%2,%3};"
        : "+f"(d[0]), "+f"(d[1]), "+f"(d[2]), "+f"(d[3])
        : "r"(a[0]), "r"(a[1]), "r"(a[2]), "r"(a[3]), "r"(b[0]), "r"(b[1]));
}
__device__ __forceinline__ uint32_t smem_u32(const void* p) {
    uint32_t a;
    asm("{ .reg .u64 t; cvta.to.shared.u64 t, %1; cvt.u32.u64 %0, t; }" : "=r"(a) : "l"(p));
    return a;
}
__device__ __forceinline__ void cp16(uint32_t dst, const void* src) {
    asm volatile("cp.async.cg.shared.global [%0], [%1], 16;" :: "r"(dst), "l"(src));
}
__device__ __forceinline__ void cp_commit() {
    asm volatile("cp.async.commit_group;" ::: "memory");
}
template<int N>
__device__ __forceinline__ void cp_wait() {
    asm volatile("cp.async.wait_group %0;" :: "n"(N) : "memory");
}

// ---------------- weight prep: transpose [K][N] -> [N][K] + bf16 split ----------------
__global__ void __launch_bounds__(256) wprep_kernel(
    const float* __restrict__ w, __nv_bfloat16* __restrict__ thi,
    __nv_bfloat16* __restrict__ tlo, int N) {
    __shared__ float t[32][33];
    int n0 = blockIdx.x * 32, k0 = blockIdx.y * 32;
    int tx = threadIdx.x & 31, ty = threadIdx.x >> 5;
#pragma unroll
    for (int i = 0; i < 4; i++)
        t[ty + 8*i][tx] = w[(size_t)(k0 + ty + 8*i) * N + n0 + tx];
    __syncthreads();
#pragma unroll
    for (int i = 0; i < 4; i++) {
        float v = t[tx][ty + 8*i];
        __nv_bfloat16 h = __float2bfloat16(v);
        __nv_bfloat16 l = __float2bfloat16(v - __bfloat162float(h));
        size_t o = (size_t)(n0 + ty + 8*i) * 1024 + k0 + tx;
        thi[o] = h; tlo[o] = l;
    }
}

// ---------------- V prep: transpose v[l][dh] -> vT[dh][l] per (b,h) + bf16 split ----------------
__global__ void __launch_bounds__(256) vprep_kernel() {
    __shared__ float t[32][33];
    int l0 = blockIdx.x * 32, d0 = blockIdx.y * 32, bh = blockIdx.z;
    int b = bh >> 4, h = bh & 15;
    int tx = threadIdx.x & 31, ty = threadIdx.x >> 5;
#pragma unroll
    for (int i = 0; i < 4; i++) {
        int l = l0 + ty + 8*i;
        t[ty + 8*i][tx] = g_qkv[((size_t)(b * LL + l)) * 3 * DDM + 2 * DDM + h * 64 + d0 + tx];
    }
    __syncthreads();
#pragma unroll
    for (int i = 0; i < 4; i++) {
        int dh = d0 + ty + 8*i;
        float v = t[tx][ty + 8*i];
        __nv_bfloat16 hh = __float2bfloat16(v);
        __nv_bfloat16 ll = __float2bfloat16(v - __bfloat162float(hh));
        size_t o = ((size_t)bh * 64 + dh) * LL + l0 + tx;
        g_vT_hi[o] = hh; g_vT_lo[o] = ll;
    }
}

// ---------------- input LayerNorm -> bf16 hi/lo split ----------------
__global__ void __launch_bounds__(256) ln_kernel(
    const float* __restrict__ x, const float* __restrict__ w, const float* __restrict__ b) {
    int row = blockIdx.x;
    int tid = threadIdx.x;
    float4 v = ((const float4*)(x + (size_t)row * DDM))[tid];
    float s  = v.x + v.y + v.z + v.w;
    float ss = v.x*v.x + v.y*v.y + v.z*v.z + v.w*v.w;
    __shared__ float rs[8], rss[8];
#pragma unroll
    for (int o = 16; o; o >>= 1) {
        s  += __shfl_xor_sync(0xffffffffu, s,  o);
        ss += __shfl_xor_sync(0xffffffffu, ss, o);
    }
    if ((tid & 31) == 0) { rs[tid >> 5] = s; rss[tid >> 5] = ss; }
    __syncthreads();
    if (tid == 0) {
        float a = 0.f, c = 0.f;
#pragma unroll
        for (int i = 0; i < 8; i++) { a += rs[i]; c += rss[i]; }
        rs[0] = a; rss[0] = c;
    }
    __syncthreads();
    float mean = rs[0] * (1.0f / DDM);
    float var  = rss[0] * (1.0f / DDM) - mean * mean;
    float rstd = rsqrtf(var + 1e-5f);
    float4 wv = ((const float4*)w)[tid];
    float4 bv = ((const float4*)b)[tid];
    float o[4];
    o[0] = (v.x - mean) * rstd * wv.x + bv.x;
    o[1] = (v.y - mean) * rstd * wv.y + bv.y;
    o[2] = (v.z - mean) * rstd * wv.z + bv.z;
    o[3] = (v.w - mean) * rstd * wv.w + bv.w;
    size_t base = (size_t)row * DDM + tid * 4;
    __nv_bfloat16 h[4], l[4];
#pragma unroll
    for (int j = 0; j < 4; j++) {
        h[j] = __float2bfloat16(o[j]);
        l[j] = __float2bfloat16(o[j] - __bfloat162float(h[j]));
    }
    *(uint2*)(g_x_hi + base) = *(uint2*)h;
    *(uint2*)(g_x_lo + base) = *(uint2*)l;
}

// ---------------- tensor GEMM via mma.sync + cp.async 2-stage pipeline ----------------
#define SPAD 20
#define ARRW (128 * SPAD)
#define STGW (4 * ARRW)
#define GEMM_SMEM_BYTES (2 * STGW * 4)   // 81920
template<int NN>
__global__ void __launch_bounds__(256) gemm_mma_kernel(
    const __nv_bfloat16* __restrict__ Ahi, const __nv_bfloat16* __restrict__ Alo,
    const __nv_bfloat16* __restrict__ Bhi, const __nv_bfloat16* __restrict__ Blo,
    float* __restrict__ C) {
    extern __shared__ uint32_t sw[];
    const uint32_t sb = smem_u32(sw);
    int tid = threadIdx.x, lane = tid & 31, wid = tid >> 5;
    int m0 = blockIdx.y * 128, n0 = blockIdx.x * 128;
    int wm = (wid & 1) * 64, wn = (wid >> 1) * 32;
    int g = lane >> 2, q = lane & 3;
    int lrow = tid >> 2, lu = tid & 3;

    float acc[4][4][4] = {};

    auto load_chunk = [&](int kc, int st) {
        uint32_t base = sb + (uint32_t)st * (STGW * 4);
#pragma unroll
        for (int h = 0; h < 2; h++) {
            int row = lrow + h * 64;
            uint32_t so = (uint32_t)(row * SPAD + lu * 4) * 4;
            size_t gA = (size_t)(m0 + row) * 1024 + kc * 32 + lu * 8;
            size_t gB = (size_t)(n0 + row) * 1024 + kc * 32 + lu * 8;
            cp16(base + 0 * ARRW * 4 + so, Ahi + gA);
            cp16(base + 1 * ARRW * 4 + so, Alo + gA);
            cp16(base + 2 * ARRW * 4 + so, Bhi + gB);
            cp16(base + 3 * ARRW * 4 + so, Blo + gB);
        }
    };

    load_chunk(0, 0);
    cp_commit();

    for (int kc = 0; kc < 32; kc++) {
        int st = kc & 1;
        if (kc < 31) { load_chunk(kc + 1, st ^ 1); cp_commit(); cp_wait<1>(); }
        else         { cp_wait<0>(); }
        __syncthreads();
        const uint32_t* pAh = sw + st * STGW + 0 * ARRW;
        const uint32_t* pAl = sw + st * STGW + 1 * ARRW;
        const uint32_t* pBh = sw + st * STGW + 2 * ARRW;
        const uint32_t* pBl = sw + st * STGW + 3 * ARRW;
#pragma unroll
        for (int ks = 0; ks < 2; ks++) {
            int kw = ks * 8 + q;
            uint32_t ah[4][4], al[4][4], bh[4][2], bl[4][2];
#pragma unroll
            for (int mf = 0; mf < 4; mf++) {
                int m = wm + mf * 16 + g;
                ah[mf][0] = pAh[m * SPAD + kw];
                ah[mf][1] = pAh[(m + 8) * SPAD + kw];
                ah[mf][2] = pAh[m * SPAD + kw + 4];
                ah[mf][3] = pAh[(m + 8) * SPAD + kw + 4];
                al[mf][0] = pAl[m * SPAD + kw];
                al[mf][1] = pAl[(m + 8) * SPAD + kw];
                al[mf][2] = pAl[m * SPAD + kw + 4];
                al[mf][3] = pAl[(m + 8) * SPAD + kw + 4];
            }
#pragma unroll
            for (int nf = 0; nf < 4; nf++) {
                int n = wn + nf * 8 + g;
                bh[nf][0] = pBh[n * SPAD + kw];
                bh[nf][1] = pBh[n * SPAD + kw + 4];
                bl[nf][0] = pBl[n * SPAD + kw];
                bl[nf][1] = pBl[n * SPAD + kw + 4];
            }
#pragma unroll
            for (int mf = 0; mf < 4; mf++)
#pragma unroll
                for (int nf = 0; nf < 4; nf++) {
                    mma_bf16(acc[mf][nf], ah[mf], bh[nf]);
                    mma_bf16(acc[mf][nf], ah[mf], bl[nf]);
                    mma_bf16(acc[mf][nf], al[mf], bh[nf]);
                }
        }
        __syncthreads();
    }
#pragma unroll
    for (int mf = 0; mf < 4; mf++)
#pragma unroll
        for (int nf = 0; nf < 4; nf++) {
            int m = m0 + wm + mf * 16 + g;
            int n = n0 + wn + nf * 8 + q * 2;
            *(float2*)&C[(size_t)m * NN + n]       = make_float2(acc[mf][nf][0], acc[mf][nf][1]);
            *(float2*)&C[(size_t)(m + 8) * NN + n] = make_float2(acc[mf][nf][2], acc[mf][nf][3]);
        }
}

// ---------------- QK LayerNorm + RoPE -> head-major bf16 hi/lo ----------------
__global__ void __launch_bounds__(256) qkln_rope_kernel(
    const float* __restrict__ qw, const float* __restrict__ kw) {
    int token = blockIdx.x;
    int tid = threadIdx.x;
    int b = token >> 11, l = token & (LL - 1);
    __shared__ float buf[DDM];
    __shared__ float rs[8], rss[8];
    for (int pass = 0; pass < 2; pass++) {
        const float* rowp = g_qkv + (size_t)token * 3 * DDM + pass * DDM;
        const float* w = pass ? kw : qw;
        float4 v = ((const float4*)rowp)[tid];
        float sm = v.x + v.y + v.z + v.w;
        float sq = v.x*v.x + v.y*v.y + v.z*v.z + v.w*v.w;
#pragma unroll
        for (int o = 16; o; o >>= 1) {
            sm += __shfl_xor_sync(0xffffffffu, sm, o);
            sq += __shfl_xor_sync(0xffffffffu, sq, o);
        }
        if ((tid & 31) == 0) { rs[tid >> 5] = sm; rss[tid >> 5] = sq; }
        __syncthreads();
        if (tid == 0) {
            float a = 0.f, c = 0.f;
#pragma unroll
            for (int i = 0; i < 8; i++) { a += rs[i]; c += rss[i]; }
            rs[0] = a; rss[0] = c;
        }
        __syncthreads();
        float mean = rs[0] * (1.0f / DDM);
        float var  = rss[0] * (1.0f / DDM) - mean * mean;
        float rstd = rsqrtf(var + 1e-5f);
        float4 wv = ((const float4*)w)[tid];
        int c0 = tid * 4;
        buf[c0 + 0] = (v.x - mean) * rstd * wv.x;
        buf[c0 + 1] = (v.y - mean) * rstd * wv.y;
        buf[c0 + 2] = (v.z - mean) * rstd * wv.z;
        buf[c0 + 3] = (v.w - mean) * rstd * wv.w;
        __syncthreads();
        __nv_bfloat16 hv[4], lv[4];
#pragma unroll
        for (int j = 0; j < 4; j++) {
            int c = c0 + j;
            int d = c & 63;
            int i2 = d & 31;
            float cs = g_cs[l * 32 + i2];
            float sn = g_sn[l * 32 + i2];
            float rot = (d < 32) ? -buf[c + 32] : buf[c - 32];
            float o = buf[c] * cs + rot * sn;
            hv[j] = __float2bfloat16(o);
            lv[j] = __float2bfloat16(o - __bfloat162float(hv[j]));
        }
        int h = c0 >> 6;
        size_t off = (((size_t)b * HH + h) * LL + l) * 64 + (c0 & 63);
        if (pass == 0) {
            *(uint2*)(g_q_hi + off) = *(uint2*)hv;
            *(uint2*)(g_q_lo + off) = *(uint2*)lv;
        } else {
            *(uint2*)(g_k_hi + off) = *(uint2*)hv;
            *(uint2*)(g_k_lo + off) = *(uint2*)lv;
        }
        __syncthreads();
    }
}

// ---------------- tensorized flash attention, 64x64 tiles ----------------
#define APAD 36   // word pitch for 64x64 bf16 tiles: (4g+q) bank map, conflict-free
struct AttnSmem {
    uint32_t Qh[64*APAD], Ql[64*APAD];
    uint32_t Kh[64*APAD], Kl[64*APAD];
    uint32_t Vh[64*APAD], Vl[64*APAD];   // V^T tiles: [dh][l]
    uint32_t Ph[64*APAD], Pl[64*APAD];
    float Ss[64][65];
    float mrow[64], lrow[64], alpha[64];
    int   sidq[64], sidk[64];
};

__global__ void __launch_bounds__(256) attn_kernel() {
    extern __shared__ char smem_raw[];
    AttnSmem& sm = *(AttnSmem*)smem_raw;
    int tid = threadIdx.x, lane = tid & 31, wid = tid >> 5;
    int wm = (wid & 1) * 32, wn = (wid >> 1) * 16;   // warp grid 2(m) x 4(n)
    int g = lane >> 2, q = lane & 3;
    int q0 = blockIdx.x * 64;
    int bh = blockIdx.y;
    int b = bh >> 4;

    // contiguous 64x64 bf16 tile -> pitch-APAD words
    auto load_tile = [&](uint32_t* dst, const __nv_bfloat16* src, int rstride) {
#pragma unroll
        for (int i = 0; i < 2; i++) {
            int u = tid + i * 256;
            int row = u >> 3, wq = (u & 7) * 4;
            uint4 v = *(const uint4*)(src + (size_t)row * rstride + wq * 2);
            *(uint4*)&dst[row * APAD + wq] = v;
        }
    };

    const __nv_bfloat16* qbh = g_q_hi + ((size_t)bh * LL + q0) * 64;
    const __nv_bfloat16* qbl = g_q_lo + ((size_t)bh * LL + q0) * 64;
    load_tile(sm.Qh, qbh, 64);
    load_tile(sm.Ql, qbl, 64);
    if (tid < 64) {
        sm.sidq[tid] = g_sid[b * LL + q0 + tid];
        sm.mrow[tid] = -INFINITY;
        sm.lrow[tid] = 0.f;
    }

    float O[2][2][4] = {};

    for (int kt = 0; kt < LL / 64; kt++) {
        if (tid >= 64 && tid < 128)
            sm.sidk[tid - 64] = g_sid[b * LL + kt * 64 + (tid - 64)];
        __syncthreads();
        bool active = !(sm.sidk[63] < sm.sidq[0] || sm.sidk[0] > sm.sidq[63]);
        if (active) {
            load_tile(sm.Kh, g_k_hi + ((size_t)bh * LL + kt * 64) * 64, 64);
            load_tile(sm.Kl, g_k_lo + ((size_t)bh * LL + kt * 64) * 64, 64);
            load_tile(sm.Vh, g_vT_hi + (size_t)bh * 64 * LL + kt * 64, LL);
            load_tile(sm.Vl, g_vT_lo + (size_t)bh * 64 * LL + kt * 64, LL);
            __syncthreads();

            // ---- S = Q @ K^T, 3-term bf16 split ----
            float sacc[2][2][4] = {};
#pragma unroll
            for (int ks = 0; ks < 4; ks++) {
                int kw = ks * 8 + q;
                uint32_t aH[2][4], aL[2][4], bH[2][2], bL[2][2];
#pragma unroll
                for (int mf = 0; mf < 2; mf++) {
                    int m = wm + mf * 16 + g;
                    aH[mf][0] = sm.Qh[m * APAD + kw];
                    aH[mf][1] = sm.Qh[(m + 8) * APAD + kw];
                    aH[mf][2] = sm.Qh[m * APAD + kw + 4];
                    aH[mf][3] = sm.Qh[(m + 8) * APAD + kw + 4];
                    aL[mf][0] = sm.Ql[m * APAD + kw];
                    aL[mf][1] = sm.Ql[(m + 8) * APAD + kw];
                    aL[mf][2] = sm.Ql[m * APAD + kw + 4];
                    aL[mf][3] = sm.Ql[(m + 8) * APAD + kw + 4];
                }
#pragma unroll
                for (int nf = 0; nf < 2; nf++) {
                    int n = wn + nf * 8 + g;
                    bH[nf][0] = sm.Kh[n * APAD + kw];
                    bH[nf][1] = sm.Kh[n * APAD + kw + 4];
                    bL[nf][0] = sm.Kl[n * APAD + kw];
                    bL[nf][1] = sm.Kl[n * APAD + kw + 4];
                }
#pragma unroll
                for (int mf = 0; mf < 2; mf++)
#pragma unroll
                    for (int nf = 0; nf < 2; nf++) {
                        mma_bf16(sacc[mf][nf], aH[mf], bH[nf]);
                        mma_bf16(sacc[mf][nf], aH[mf], bL[nf]);
                        mma_bf16(sacc[mf][nf], aL[mf], bH[nf]);
                    }
            }
            // write S to smem with scale + packed-seq mask
#pragma unroll
            for (int mf = 0; mf < 2; mf++)
#pragma unroll
                for (int nf = 0; nf < 2; nf++) {
                    int r = wm + mf * 16 + g, c = wn + nf * 8 + 2 * q;
#pragma unroll
                    for (int e = 0; e < 4; e++) {
                        int rr = r + (e >> 1) * 8, cc = c + (e & 1);
                        float sv = sacc[mf][nf][e] * 0.125f;
                        if (sm.sidq[rr] != sm.sidk[cc]) sv = -1e30f;
                        sm.Ss[rr][cc] = sv;
                    }
                }
            __syncthreads();

            // ---- online softmax: 4 threads per row, 16 consecutive cols each ----
            {
                int r = tid >> 2, sub = tid & 3;
                float mloc = -INFINITY;
#pragma unroll
                for (int c = sub * 16; c < sub * 16 + 16; c++)
                    mloc = fmaxf(mloc, sm.Ss[r][c]);
                mloc = fmaxf(mloc, __shfl_xor_sync(0xffffffffu, mloc, 1));
                mloc = fmaxf(mloc, __shfl_xor_sync(0xffffffffu, mloc, 2));
                float mold = sm.mrow[r];
                float mnew = fmaxf(mold, mloc);
                float ls = 0.f;
#pragma unroll
                for (int w = sub * 8; w < sub * 8 + 8; w++) {
                    float p0 = __expf(sm.Ss[r][2 * w]     - mnew);
                    float p1 = __expf(sm.Ss[r][2 * w + 1] - mnew);
                    ls += p0 + p1;
                    float h0 = __bfloat162float(__float2bfloat16(p0));
                    float h1 = __bfloat162float(__float2bfloat16(p1));
                    sm.Ph[r * APAD + w] = bf16pack(h0, h1);
                    sm.Pl[r * APAD + w] = bf16pack(p0 - h0, p1 - h1);
                }
                ls += __shfl_xor_sync(0xffffffffu, ls, 1);
                ls += __shfl_xor_sync(0xffffffffu, ls, 2);
                if (sub == 0) {
                    float a = __expf(mold - mnew);
                    sm.alpha[r] = a;
                    sm.lrow[r] = sm.lrow[r] * a + ls;
                    sm.mrow[r] = mnew;
                }
            }
            __syncthreads();

            // ---- O = O*alpha + P @ V, 3-term bf16 split ----
#pragma unroll
            for (int mf = 0; mf < 2; mf++) {
                float a0 = sm.alpha[wm + mf * 16 + g];
                float a1 = sm.alpha[wm + mf * 16 + g + 8];
#pragma unroll
                for (int nf = 0; nf < 2; nf++) {
                    O[mf][nf][0] *= a0; O[mf][nf][1] *= a0;
                    O[mf][nf][2] *= a1; O[mf][nf][3] *= a1;
                }
            }
#pragma unroll
            for (int ks = 0; ks < 4; ks++) {
                int kw = ks * 8 + q;
                uint32_t aH[2][4], aL[2][4], bH[2][2], bL[2][2];
#pragma unroll
                for (int mf = 0; mf < 2; mf++) {
                    int m = wm + mf * 16 + g;
                    aH[mf][0] = sm.Ph[m * APAD + kw];
                    aH[mf][1] = sm.Ph[(m + 8) * APAD + kw];
                    aH[mf][2] = sm.Ph[m * APAD + kw + 4];
                    aH[mf][3] = sm.Ph[(m + 8) * APAD + kw + 4];
                    aL[mf][0] = sm.Pl[m * APAD + kw];
                    aL[mf][1] = sm.Pl[(m + 8) * APAD + kw];
                    aL[mf][2] = sm.Pl[m * APAD + kw + 4];
                    aL[mf][3] = sm.Pl[(m + 8) * APAD + kw + 4];
                }
#pragma unroll
                for (int nf = 0; nf < 2; nf++) {
                    int n = wn + nf * 8 + g;
                    bH[nf][0] = sm.Vh[n * APAD + kw];
                    bH[nf][1] = sm.Vh[n * APAD + kw + 4];
                    bL[nf][0] = sm.Vl[n * APAD + kw];
                    bL[nf][1] = sm.Vl[n * APAD + kw + 4];
                }
#pragma unroll
                for (int mf = 0; mf < 2; mf++)
#pragma unroll
                    for (int nf = 0; nf < 2; nf++) {
                        mma_bf16(O[mf][nf], aH[mf], bH[nf]);
                        mma_bf16(O[mf][nf], aH[mf], bL[nf]);
                        mma_bf16(O[mf][nf], aL[mf], bH[nf]);
                    }
            }
        }
        __syncthreads();
    }

    // ---- epilogue: normalize + bf16 hi/lo split for out-projection ----
    int h = bh & 15;
#pragma unroll
    for (int mf = 0; mf < 2; mf++)
#pragma unroll
        for (int nf = 0; nf < 2; nf++) {
            int r = wm + mf * 16 + g, c = wn + nf * 8 + 2 * q;
#pragma unroll
            for (int half = 0; half < 2; half++) {
                int rr = r + half * 8;
                float il = 1.0f / sm.lrow[rr];
                float o0 = O[mf][nf][half * 2 + 0] * il;
                float o1 = O[mf][nf][half * 2 + 1] * il;
                float h0 = __bfloat162float(__float2bfloat16(o0));
                float h1 = __bfloat162float(__float2bfloat16(o1));
                size_t off = ((size_t)(b * LL + q0 + rr)) * DDM + h * 64 + c;
                *(uint32_t*)(g_ctx_hi + off) = bf16pack(h0, h1);
                *(uint32_t*)(g_ctx_lo + off) = bf16pack(o0 - h0, o1 - h1);
            }
        }
}

// ---------------- launch ----------------
extern "C" void kernel_launch(void* const* d_in, const int* in_sizes, int n_in,
                              void* d_out, int out_size) {
    (void)in_sizes; (void)n_in; (void)out_size;
    const float* x      = (const float*)d_in[0];
    const void*  seq    = d_in[1];
    const float* ln_w   = (const float*)d_in[2];
    const float* ln_b   = (const float*)d_in[3];
    const float* w_qkv  = (const float*)d_in[4];
    const float* q_ln_w = (const float*)d_in[5];
    const float* k_ln_w = (const float*)d_in[6];
    const float* w_out  = (const float*)d_in[7];
    float* out = (float*)d_out;

    float* p_qkv;
    __nv_bfloat16 *p_xh, *p_xl, *p_ch, *p_cl, *p_wqh, *p_wql, *p_woh, *p_wol;
    cudaGetSymbolAddress((void**)&p_qkv, g_qkv);
    cudaGetSymbolAddress((void**)&p_xh,  g_x_hi);
    cudaGetSymbolAddress((void**)&p_xl,  g_x_lo);
    cudaGetSymbolAddress((void**)&p_ch,  g_ctx_hi);
    cudaGetSymbolAddress((void**)&p_cl,  g_ctx_lo);
    cudaGetSymbolAddress((void**)&p_wqh, g_wqkv_hi);
    cudaGetSymbolAddress((void**)&p_wql, g_wqkv_lo);
    cudaGetSymbolAddress((void**)&p_woh, g_wout_hi);
    cudaGetSymbolAddress((void**)&p_wol, g_wout_lo);

    cudaFuncSetAttribute(gemm_mma_kernel<3 * DDM>, cudaFuncAttributeMaxDynamicSharedMemorySize, GEMM_SMEM_BYTES);
    cudaFuncSetAttribute(gemm_mma_kernel<DDM>, cudaFuncAttributeMaxDynamicSharedMemorySize, GEMM_SMEM_BYTES);
    int attn_smem = (int)sizeof(AttnSmem);
    cudaFuncSetAttribute(attn_kernel, cudaFuncAttributeMaxDynamicSharedMemorySize, attn_smem);

    sid_norm_kernel<<<(NT + 255) / 256, 256>>>(seq);
    rope_table_kernel<<<(LL * 32 + 255) / 256, 256>>>();
    wprep_kernel<<<dim3(3 * DDM / 32, DDM / 32), 256>>>(w_qkv, p_wqh, p_wql, 3 * DDM);
    wprep_kernel<<<dim3(DDM / 32, DDM / 32), 256>>>(w_out, p_woh, p_wol, DDM);
    ln_kernel<<<NT, 256>>>(x, ln_w, ln_b);
    gemm_mma_kernel<3 * DDM><<<dim3(3 * DDM / 128, NT / 128), 256, GEMM_SMEM_BYTES>>>(p_xh, p_xl, p_wqh, p_wql, p_qkv);
    qkln_rope_kernel<<<NT, 256>>>(q_ln_w, k_ln_w);
    vprep_kernel<<<dim3(LL / 32, 2, BB * HH), 256>>>();
    attn_kernel<<<dim3(LL / 64, BB * HH), 256, attn_smem>>>();
    gemm_mma_kernel<DDM><<<dim3(DDM / 128, NT / 128), 256, GEMM_SMEM_BYTES>>>(p_ch, p_cl, p_woh, p_wol, out);
}

// round 7
// speedup vs baseline: 2.2634x; 1.0480x over previous
#include <cuda_runtime.h>
#include <cuda_bf16.h>
#include <math.h>
#include <cstdint>

#define BB 4
#define LL 2048
#define DDM 1024
#define HH 16
#define NT (BB*LL)   // 8192 tokens

// ---------------- scratch (device globals: allocation-free rule) ----------------
__device__ float          g_qkv[(size_t)NT * 3 * DDM];      // 96 MB fp32
__device__ __nv_bfloat16  g_x_hi[(size_t)NT * DDM];         // LN output split
__device__ __nv_bfloat16  g_x_lo[(size_t)NT * DDM];
__device__ __nv_bfloat16  g_ctx_hi[(size_t)NT * DDM];       // attention output split
__device__ __nv_bfloat16  g_ctx_lo[(size_t)NT * DDM];
__device__ __nv_bfloat16  g_wqkv_hi[(size_t)3 * DDM * DDM]; // w_qkv^T [3072][1024]
__device__ __nv_bfloat16  g_wqkv_lo[(size_t)3 * DDM * DDM];
__device__ __nv_bfloat16  g_wout_hi[(size_t)DDM * DDM];     // w_out^T [1024][1024]
__device__ __nv_bfloat16  g_wout_lo[(size_t)DDM * DDM];
// head-major attention operands [b,h,l,64] (q,k) and [b,h,dh,l] (vT)
__device__ __nv_bfloat16  g_q_hi[(size_t)NT * 64 * HH];
__device__ __nv_bfloat16  g_q_lo[(size_t)NT * 64 * HH];
__device__ __nv_bfloat16  g_k_hi[(size_t)NT * 64 * HH];
__device__ __nv_bfloat16  g_k_lo[(size_t)NT * 64 * HH];
__device__ __nv_bfloat16  g_vT_hi[(size_t)NT * 64 * HH];
__device__ __nv_bfloat16  g_vT_lo[(size_t)NT * 64 * HH];
__device__ float g_cs[LL * 32];
__device__ float g_sn[LL * 32];
__device__ int   g_sid[NT];

// ---------------- sequence_id dtype sniff + normalize ----------------
__global__ void sid_norm_kernel(const void* __restrict__ seqraw) {
    const int* w = (const int*)seqraw;
    bool is64 = (w[2*1000+1] == 0) && (w[2*1500+1] == 0) && (w[2*2047+1] == 0);
    int i = blockIdx.x * blockDim.x + threadIdx.x;
    if (i < NT) g_sid[i] = is64 ? w[2*i] : w[i];
}

// ---------------- rope tables (fp64 for angle accuracy) ----------------
__global__ void rope_table_kernel() {
    int idx = blockIdx.x * blockDim.x + threadIdx.x;
    if (idx >= LL * 32) return;
    int s = idx >> 5, i = idx & 31;
    double ang = (double)s * pow(10000.0, -(double)i / 32.0);
    g_cs[idx] = (float)cos(ang);
    g_sn[idx] = (float)sin(ang);
}

// ---------------- helpers ----------------
__device__ __forceinline__ uint32_t bf16pack(float a, float b) {
    __nv_bfloat16 ha = __float2bfloat16(a), hb = __float2bfloat16(b);
    uint32_t r = ((uint32_t)*(uint16_t*)&hb << 16) | (uint32_t)*(uint16_t*)&ha;
    return r;
}
__device__ __forceinline__ void mma_bf16(float* d, const uint32_t* a, const uint32_t* b) {
    asm volatile(
        "mma.sync.aligned.m16n8k16.row.col.f32.bf16.bf16.f32 "
        "{%0,%1,%2,%3}, {%4,%5,%6,%7}, {%8,%9}, {%0,%1,%2,%3};"
        : "+f"(d[0]), "+f"(d[1]), "+f"(d[2]), "+f"(d[3])
        : "r"(a[0]), "r"(a[1]), "r"(a[2]), "r"(a[3]), "r"(b[0]), "r"(b[1]));
}
__device__ __forceinline__ void ldsm4(uint32_t* r, uint32_t a) {
    asm volatile("ldmatrix.sync.aligned.m8n8.x4.shared.b16 {%0,%1,%2,%3}, [%4];"
        : "=r"(r[0]), "=r"(r[1]), "=r"(r[2]), "=r"(r[3]) : "r"(a));
}
__device__ __forceinline__ void ldsm2(uint32_t* r, uint32_t a) {
    asm volatile("ldmatrix.sync.aligned.m8n8.x2.shared.b16 {%0,%1}, [%2];"
        : "=r"(r[0]), "=r"(r[1]) : "r"(a));
}
__device__ __forceinline__ uint32_t smem_u32(const void* p) {
    uint32_t a;
    asm("{ .reg .u64 t; cvta.to.shared.u64 t, %1; cvt.u32.u64 %0, t; }" : "=r"(a) : "l"(p));
    return a;
}
__device__ __forceinline__ void cp16(uint32_t dst, const void* src) {
    asm volatile("cp.async.cg.shared.global [%0], [%1], 16;" :: "r"(dst), "l"(src));
}
__device__ __forceinline__ void cp_commit() {
    asm volatile("cp.async.commit_group;" ::: "memory");
}
template<int N>
__device__ __forceinline__ void cp_wait() {
    asm volatile("cp.async.wait_group %0;" :: "n"(N) : "memory");
}

// ---------------- weight prep: transpose [K][N] -> [N][K] + bf16 split ----------------
__global__ void __launch_bounds__(256) wprep_kernel(
    const float* __restrict__ w, __nv_bfloat16* __restrict__ thi,
    __nv_bfloat16* __restrict__ tlo, int N) {
    __shared__ float t[32][33];
    int n0 = blockIdx.x * 32, k0 = blockIdx.y * 32;
    int tx = threadIdx.x & 31, ty = threadIdx.x >> 5;
#pragma unroll
    for (int i = 0; i < 4; i++)
        t[ty + 8*i][tx] = w[(size_t)(k0 + ty + 8*i) * N + n0 + tx];
    __syncthreads();
#pragma unroll
    for (int i = 0; i < 4; i++) {
        float v = t[tx][ty + 8*i];
        __nv_bfloat16 h = __float2bfloat16(v);
        __nv_bfloat16 l = __float2bfloat16(v - __bfloat162float(h));
        size_t o = (size_t)(n0 + ty + 8*i) * 1024 + k0 + tx;
        thi[o] = h; tlo[o] = l;
    }
}

// ---------------- V prep: transpose v[l][dh] -> vT[dh][l] per (b,h) + bf16 split ----------------
__global__ void __launch_bounds__(256) vprep_kernel() {
    __shared__ float t[32][33];
    int l0 = blockIdx.x * 32, d0 = blockIdx.y * 32, bh = blockIdx.z;
    int b = bh >> 4, h = bh & 15;
    int tx = threadIdx.x & 31, ty = threadIdx.x >> 5;
#pragma unroll
    for (int i = 0; i < 4; i++) {
        int l = l0 + ty + 8*i;
        t[ty + 8*i][tx] = g_qkv[((size_t)(b * LL + l)) * 3 * DDM + 2 * DDM + h * 64 + d0 + tx];
    }
    __syncthreads();
#pragma unroll
    for (int i = 0; i < 4; i++) {
        int dh = d0 + ty + 8*i;
        float v = t[tx][ty + 8*i];
        __nv_bfloat16 hh = __float2bfloat16(v);
        __nv_bfloat16 ll = __float2bfloat16(v - __bfloat162float(hh));
        size_t o = ((size_t)bh * 64 + dh) * LL + l0 + tx;
        g_vT_hi[o] = hh; g_vT_lo[o] = ll;
    }
}

// ---------------- input LayerNorm -> bf16 hi/lo split ----------------
__global__ void __launch_bounds__(256) ln_kernel(
    const float* __restrict__ x, const float* __restrict__ w, const float* __restrict__ b) {
    int row = blockIdx.x;
    int tid = threadIdx.x;
    float4 v = ((const float4*)(x + (size_t)row * DDM))[tid];
    float s  = v.x + v.y + v.z + v.w;
    float ss = v.x*v.x + v.y*v.y + v.z*v.z + v.w*v.w;
    __shared__ float rs[8], rss[8];
#pragma unroll
    for (int o = 16; o; o >>= 1) {
        s  += __shfl_xor_sync(0xffffffffu, s,  o);
        ss += __shfl_xor_sync(0xffffffffu, ss, o);
    }
    if ((tid & 31) == 0) { rs[tid >> 5] = s; rss[tid >> 5] = ss; }
    __syncthreads();
    if (tid == 0) {
        float a = 0.f, c = 0.f;
#pragma unroll
        for (int i = 0; i < 8; i++) { a += rs[i]; c += rss[i]; }
        rs[0] = a; rss[0] = c;
    }
    __syncthreads();
    float mean = rs[0] * (1.0f / DDM);
    float var  = rss[0] * (1.0f / DDM) - mean * mean;
    float rstd = rsqrtf(var + 1e-5f);
    float4 wv = ((const float4*)w)[tid];
    float4 bv = ((const float4*)b)[tid];
    float o[4];
    o[0] = (v.x - mean) * rstd * wv.x + bv.x;
    o[1] = (v.y - mean) * rstd * wv.y + bv.y;
    o[2] = (v.z - mean) * rstd * wv.z + bv.z;
    o[3] = (v.w - mean) * rstd * wv.w + bv.w;
    size_t base = (size_t)row * DDM + tid * 4;
    __nv_bfloat16 h[4], l[4];
#pragma unroll
    for (int j = 0; j < 4; j++) {
        h[j] = __float2bfloat16(o[j]);
        l[j] = __float2bfloat16(o[j] - __bfloat162float(h[j]));
    }
    *(uint2*)(g_x_hi + base) = *(uint2*)h;
    *(uint2*)(g_x_lo + base) = *(uint2*)l;
}

// ---------------- tensor GEMM via mma.sync + cp.async pipeline + ldmatrix ----------------
#define SPAD 20
#define ARRW (128 * SPAD)
#define STGW (4 * ARRW)
#define GEMM_SMEM_BYTES (2 * STGW * 4)   // 81920
template<int NN>
__global__ void __launch_bounds__(256) gemm_mma_kernel(
    const __nv_bfloat16* __restrict__ Ahi, const __nv_bfloat16* __restrict__ Alo,
    const __nv_bfloat16* __restrict__ Bhi, const __nv_bfloat16* __restrict__ Blo,
    float* __restrict__ C) {
    extern __shared__ uint32_t sw[];
    const uint32_t sb = smem_u32(sw);
    int tid = threadIdx.x, lane = tid & 31, wid = tid >> 5;
    int m0 = blockIdx.y * 128, n0 = blockIdx.x * 128;
    int wm = (wid & 1) * 64, wn = (wid >> 1) * 32;
    int g = lane >> 2, q = lane & 3;
    int lrow = tid >> 2, lu = tid & 3;
    int lr = lane & 7, sel = lane >> 3;

    // ldmatrix per-lane address offsets (bytes) within one array
    uint32_t aoff[4], boff[4];
#pragma unroll
    for (int mf = 0; mf < 4; mf++)
        aoff[mf] = (uint32_t)((wm + mf * 16 + (sel & 1) * 8 + lr) * SPAD + (sel >> 1) * 4) * 4;
#pragma unroll
    for (int nf = 0; nf < 4; nf++)
        boff[nf] = (uint32_t)((wn + nf * 8 + lr) * SPAD + (sel & 1) * 4) * 4;

    float acc[4][4][4] = {};

    auto load_chunk = [&](int kc, int st) {
        uint32_t base = sb + (uint32_t)st * (STGW * 4);
#pragma unroll
        for (int h = 0; h < 2; h++) {
            int row = lrow + h * 64;
            uint32_t so = (uint32_t)(row * SPAD + lu * 4) * 4;
            size_t gA = (size_t)(m0 + row) * 1024 + kc * 32 + lu * 8;
            size_t gB = (size_t)(n0 + row) * 1024 + kc * 32 + lu * 8;
            cp16(base + 0 * ARRW * 4 + so, Ahi + gA);
            cp16(base + 1 * ARRW * 4 + so, Alo + gA);
            cp16(base + 2 * ARRW * 4 + so, Bhi + gB);
            cp16(base + 3 * ARRW * 4 + so, Blo + gB);
        }
    };

    load_chunk(0, 0);
    cp_commit();

    for (int kc = 0; kc < 32; kc++) {
        int st = kc & 1;
        if (kc < 31) { load_chunk(kc + 1, st ^ 1); cp_commit(); cp_wait<1>(); }
        else         { cp_wait<0>(); }
        __syncthreads();
        uint32_t stb = sb + (uint32_t)st * (STGW * 4);
        uint32_t bAh = stb, bAl = stb + ARRW * 4, bBh = stb + 2 * ARRW * 4, bBl = stb + 3 * ARRW * 4;
#pragma unroll
        for (int ks = 0; ks < 2; ks++) {
            uint32_t ko = ks * 32;   // 8 words = 16 bf16 per k-step
            uint32_t ah[4][4], al[4][4], bh[4][2], bl[4][2];
#pragma unroll
            for (int mf = 0; mf < 4; mf++) {
                ldsm4(ah[mf], bAh + aoff[mf] + ko);
                ldsm4(al[mf], bAl + aoff[mf] + ko);
            }
#pragma unroll
            for (int nf = 0; nf < 4; nf++) {
                ldsm2(bh[nf], bBh + boff[nf] + ko);
                ldsm2(bl[nf], bBl + boff[nf] + ko);
            }
#pragma unroll
            for (int mf = 0; mf < 4; mf++)
#pragma unroll
                for (int nf = 0; nf < 4; nf++) {
                    mma_bf16(acc[mf][nf], ah[mf], bh[nf]);
                    mma_bf16(acc[mf][nf], ah[mf], bl[nf]);
                    mma_bf16(acc[mf][nf], al[mf], bh[nf]);
                }
        }
        __syncthreads();
    }
#pragma unroll
    for (int mf = 0; mf < 4; mf++)
#pragma unroll
        for (int nf = 0; nf < 4; nf++) {
            int m = m0 + wm + mf * 16 + g;
            int n = n0 + wn + nf * 8 + q * 2;
            *(float2*)&C[(size_t)m * NN + n]       = make_float2(acc[mf][nf][0], acc[mf][nf][1]);
            *(float2*)&C[(size_t)(m + 8) * NN + n] = make_float2(acc[mf][nf][2], acc[mf][nf][3]);
        }
}

// ---------------- QK LayerNorm + RoPE -> head-major bf16 hi/lo ----------------
__global__ void __launch_bounds__(256) qkln_rope_kernel(
    const float* __restrict__ qw, const float* __restrict__ kw) {
    int token = blockIdx.x;
    int tid = threadIdx.x;
    int b = token >> 11, l = token & (LL - 1);
    __shared__ float buf[DDM];
    __shared__ float rs[8], rss[8];
    for (int pass = 0; pass < 2; pass++) {
        const float* rowp = g_qkv + (size_t)token * 3 * DDM + pass * DDM;
        const float* w = pass ? kw : qw;
        float4 v = ((const float4*)rowp)[tid];
        float sm = v.x + v.y + v.z + v.w;
        float sq = v.x*v.x + v.y*v.y + v.z*v.z + v.w*v.w;
#pragma unroll
        for (int o = 16; o; o >>= 1) {
            sm += __shfl_xor_sync(0xffffffffu, sm, o);
            sq += __shfl_xor_sync(0xffffffffu, sq, o);
        }
        if ((tid & 31) == 0) { rs[tid >> 5] = sm; rss[tid >> 5] = sq; }
        __syncthreads();
        if (tid == 0) {
            float a = 0.f, c = 0.f;
#pragma unroll
            for (int i = 0; i < 8; i++) { a += rs[i]; c += rss[i]; }
            rs[0] = a; rss[0] = c;
        }
        __syncthreads();
        float mean = rs[0] * (1.0f / DDM);
        float var  = rss[0] * (1.0f / DDM) - mean * mean;
        float rstd = rsqrtf(var + 1e-5f);
        float4 wv = ((const float4*)w)[tid];
        int c0 = tid * 4;
        buf[c0 + 0] = (v.x - mean) * rstd * wv.x;
        buf[c0 + 1] = (v.y - mean) * rstd * wv.y;
        buf[c0 + 2] = (v.z - mean) * rstd * wv.z;
        buf[c0 + 3] = (v.w - mean) * rstd * wv.w;
        __syncthreads();
        __nv_bfloat16 hv[4], lv[4];
#pragma unroll
        for (int j = 0; j < 4; j++) {
            int c = c0 + j;
            int d = c & 63;
            int i2 = d & 31;
            float cs = g_cs[l * 32 + i2];
            float sn = g_sn[l * 32 + i2];
            float rot = (d < 32) ? -buf[c + 32] : buf[c - 32];
            float o = buf[c] * cs + rot * sn;
            hv[j] = __float2bfloat16(o);
            lv[j] = __float2bfloat16(o - __bfloat162float(hv[j]));
        }
        int h = c0 >> 6;
        size_t off = (((size_t)b * HH + h) * LL + l) * 64 + (c0 & 63);
        if (pass == 0) {
            *(uint2*)(g_q_hi + off) = *(uint2*)hv;
            *(uint2*)(g_q_lo + off) = *(uint2*)lv;
        } else {
            *(uint2*)(g_k_hi + off) = *(uint2*)hv;
            *(uint2*)(g_k_lo + off) = *(uint2*)lv;
        }
        __syncthreads();
    }
}

// ---------------- tensorized flash attention, 64x64 tiles ----------------
#define APAD 36   // word pitch for 64x64 bf16 tiles: conflict-free
struct AttnSmem {
    uint32_t Qh[64*APAD], Ql[64*APAD];
    uint32_t Kh[64*APAD], Kl[64*APAD];
    uint32_t Vh[64*APAD], Vl[64*APAD];   // V^T tiles: [dh][l]
    uint32_t Ph[64*APAD], Pl[64*APAD];
    float Ss[64][65];
    float mrow[64], lrow[64], alpha[64];
    int   sidq[64], sidk[64];
};

__global__ void __launch_bounds__(256) attn_kernel() {
    extern __shared__ char smem_raw[];
    AttnSmem& sm = *(AttnSmem*)smem_raw;
    int tid = threadIdx.x, lane = tid & 31, wid = tid >> 5;
    int wm = (wid & 1) * 32, wn = (wid >> 1) * 16;   // warp grid 2(m) x 4(n)
    int g = lane >> 2, q = lane & 3;
    int lr = lane & 7, sel = lane >> 3;
    int q0 = blockIdx.x * 64;
    int bh = blockIdx.y;
    int b = bh >> 4;

    // ldmatrix offsets (bytes) within one 64xAPAD array
    uint32_t aoffA[2], boffB[2];
#pragma unroll
    for (int mf = 0; mf < 2; mf++)
        aoffA[mf] = (uint32_t)((wm + mf * 16 + (sel & 1) * 8 + lr) * APAD + (sel >> 1) * 4) * 4;
#pragma unroll
    for (int nf = 0; nf < 2; nf++)
        boffB[nf] = (uint32_t)((wn + nf * 8 + lr) * APAD + (sel & 1) * 4) * 4;

    const uint32_t uQh = smem_u32(sm.Qh), uQl = smem_u32(sm.Ql);
    const uint32_t uKh = smem_u32(sm.Kh), uKl = smem_u32(sm.Kl);
    const uint32_t uVh = smem_u32(sm.Vh), uVl = smem_u32(sm.Vl);
    const uint32_t uPh = smem_u32(sm.Ph), uPl = smem_u32(sm.Pl);

    auto load_tile = [&](uint32_t* dst, const __nv_bfloat16* src, int rstride) {
#pragma unroll
        for (int i = 0; i < 2; i++) {
            int u = tid + i * 256;
            int row = u >> 3, wq = (u & 7) * 4;
            uint4 v = *(const uint4*)(src + (size_t)row * rstride + wq * 2);
            *(uint4*)&dst[row * APAD + wq] = v;
        }
    };

    load_tile(sm.Qh, g_q_hi + ((size_t)bh * LL + q0) * 64, 64);
    load_tile(sm.Ql, g_q_lo + ((size_t)bh * LL + q0) * 64, 64);
    if (tid < 64) {
        sm.sidq[tid] = g_sid[b * LL + q0 + tid];
        sm.mrow[tid] = -INFINITY;
        sm.lrow[tid] = 0.f;
    }

    float O[2][2][4] = {};

    for (int kt = 0; kt < LL / 64; kt++) {
        if (tid >= 64 && tid < 128)
            sm.sidk[tid - 64] = g_sid[b * LL + kt * 64 + (tid - 64)];
        __syncthreads();
        bool active = !(sm.sidk[63] < sm.sidq[0] || sm.sidk[0] > sm.sidq[63]);
        if (active) {
            load_tile(sm.Kh, g_k_hi + ((size_t)bh * LL + kt * 64) * 64, 64);
            load_tile(sm.Kl, g_k_lo + ((size_t)bh * LL + kt * 64) * 64, 64);
            load_tile(sm.Vh, g_vT_hi + (size_t)bh * 64 * LL + kt * 64, LL);
            load_tile(sm.Vl, g_vT_lo + (size_t)bh * 64 * LL + kt * 64, LL);
            __syncthreads();

            // ---- S = Q @ K^T, 3-term bf16 split ----
            float sacc[2][2][4] = {};
#pragma unroll
            for (int ks = 0; ks < 4; ks++) {
                uint32_t ko = ks * 32;
                uint32_t aH[2][4], aL[2][4], bH[2][2], bL[2][2];
#pragma unroll
                for (int mf = 0; mf < 2; mf++) {
                    ldsm4(aH[mf], uQh + aoffA[mf] + ko);
                    ldsm4(aL[mf], uQl + aoffA[mf] + ko);
                }
#pragma unroll
                for (int nf = 0; nf < 2; nf++) {
                    ldsm2(bH[nf], uKh + boffB[nf] + ko);
                    ldsm2(bL[nf], uKl + boffB[nf] + ko);
                }
#pragma unroll
                for (int mf = 0; mf < 2; mf++)
#pragma unroll
                    for (int nf = 0; nf < 2; nf++) {
                        mma_bf16(sacc[mf][nf], aH[mf], bH[nf]);
                        mma_bf16(sacc[mf][nf], aH[mf], bL[nf]);
                        mma_bf16(sacc[mf][nf], aL[mf], bH[nf]);
                    }
            }
            // write S to smem with scale + packed-seq mask
#pragma unroll
            for (int mf = 0; mf < 2; mf++)
#pragma unroll
                for (int nf = 0; nf < 2; nf++) {
                    int r = wm + mf * 16 + g, c = wn + nf * 8 + 2 * q;
#pragma unroll
                    for (int e = 0; e < 4; e++) {
                        int rr = r + (e >> 1) * 8, cc = c + (e & 1);
                        float sv = sacc[mf][nf][e] * 0.125f;
                        if (sm.sidq[rr] != sm.sidk[cc]) sv = -1e30f;
                        sm.Ss[rr][cc] = sv;
                    }
                }
            __syncthreads();

            // ---- online softmax: 4 threads per row ----
            {
                int r = tid >> 2, sub = tid & 3;
                float mloc = -INFINITY;
#pragma unroll
                for (int c = sub * 16; c < sub * 16 + 16; c++)
                    mloc = fmaxf(mloc, sm.Ss[r][c]);
                mloc = fmaxf(mloc, __shfl_xor_sync(0xffffffffu, mloc, 1));
                mloc = fmaxf(mloc, __shfl_xor_sync(0xffffffffu, mloc, 2));
                float mold = sm.mrow[r];
                float mnew = fmaxf(mold, mloc);
                float ls = 0.f;
#pragma unroll
                for (int w = sub * 8; w < sub * 8 + 8; w++) {
                    float p0 = __expf(sm.Ss[r][2 * w]     - mnew);
                    float p1 = __expf(sm.Ss[r][2 * w + 1] - mnew);
                    ls += p0 + p1;
                    float h0 = __bfloat162float(__float2bfloat16(p0));
                    float h1 = __bfloat162float(__float2bfloat16(p1));
                    sm.Ph[r * APAD + w] = bf16pack(h0, h1);
                    sm.Pl[r * APAD + w] = bf16pack(p0 - h0, p1 - h1);
                }
                ls += __shfl_xor_sync(0xffffffffu, ls, 1);
                ls += __shfl_xor_sync(0xffffffffu, ls, 2);
                if (sub == 0) {
                    float a = __expf(mold - mnew);
                    sm.alpha[r] = a;
                    sm.lrow[r] = sm.lrow[r] * a + ls;
                    sm.mrow[r] = mnew;
                }
            }
            __syncthreads();

            // ---- O = O*alpha + P @ V, 3-term bf16 split ----
#pragma unroll
            for (int mf = 0; mf < 2; mf++) {
                float a0 = sm.alpha[wm + mf * 16 + g];
                float a1 = sm.alpha[wm + mf * 16 + g + 8];
#pragma unroll
                for (int nf = 0; nf < 2; nf++) {
                    O[mf][nf][0] *= a0; O[mf][nf][1] *= a0;
                    O[mf][nf][2] *= a1; O[mf][nf][3] *= a1;
                }
            }
#pragma unroll
            for (int ks = 0; ks < 4; ks++) {
                uint32_t ko = ks * 32;
                uint32_t aH[2][4], aL[2][4], bH[2][2], bL[2][2];
#pragma unroll
                for (int mf = 0; mf < 2; mf++) {
                    ldsm4(aH[mf], uPh + aoffA[mf] + ko);
                    ldsm4(aL[mf], uPl + aoffA[mf] + ko);
                }
#pragma unroll
                for (int nf = 0; nf < 2; nf++) {
                    ldsm2(bH[nf], uVh + boffB[nf] + ko);
                    ldsm2(bL[nf], uVl + boffB[nf] + ko);
                }
#pragma unroll
                for (int mf = 0; mf < 2; mf++)
#pragma unroll
                    for (int nf = 0; nf < 2; nf++) {
                        mma_bf16(O[mf][nf], aH[mf], bH[nf]);
                        mma_bf16(O[mf][nf], aH[mf], bL[nf]);
                        mma_bf16(O[mf][nf], aL[mf], bH[nf]);
                    }
            }
        }
        __syncthreads();
    }

    // ---- epilogue: normalize + bf16 hi/lo split for out-projection ----
    int h = bh & 15;
#pragma unroll
    for (int mf = 0; mf < 2; mf++)
#pragma unroll
        for (int nf = 0; nf < 2; nf++) {
            int r = wm + mf * 16 + g, c = wn + nf * 8 + 2 * q;
#pragma unroll
            for (int half = 0; half < 2; half++) {
                int rr = r + half * 8;
                float il = 1.0f / sm.lrow[rr];
                float o0 = O[mf][nf][half * 2 + 0] * il;
                float o1 = O[mf][nf][half * 2 + 1] * il;
                float h0 = __bfloat162float(__float2bfloat16(o0));
                float h1 = __bfloat162float(__float2bfloat16(o1));
                size_t off = ((size_t)(b * LL + q0 + rr)) * DDM + h * 64 + c;
                *(uint32_t*)(g_ctx_hi + off) = bf16pack(h0, h1);
                *(uint32_t*)(g_ctx_lo + off) = bf16pack(o0 - h0, o1 - h1);
            }
        }
}

// ---------------- launch ----------------
extern "C" void kernel_launch(void* const* d_in, const int* in_sizes, int n_in,
                              void* d_out, int out_size) {
    (void)in_sizes; (void)n_in; (void)out_size;
    const float* x      = (const float*)d_in[0];
    const void*  seq    = d_in[1];
    const float* ln_w   = (const float*)d_in[2];
    const float* ln_b   = (const float*)d_in[3];
    const float* w_qkv  = (const float*)d_in[4];
    const float* q_ln_w = (const float*)d_in[5];
    const float* k_ln_w = (const float*)d_in[6];
    const float* w_out  = (const float*)d_in[7];
    float* out = (float*)d_out;

    float* p_qkv;
    __nv_bfloat16 *p_xh, *p_xl, *p_ch, *p_cl, *p_wqh, *p_wql, *p_woh, *p_wol;
    cudaGetSymbolAddress((void**)&p_qkv, g_qkv);
    cudaGetSymbolAddress((void**)&p_xh,  g_x_hi);
    cudaGetSymbolAddress((void**)&p_xl,  g_x_lo);
    cudaGetSymbolAddress((void**)&p_ch,  g_ctx_hi);
    cudaGetSymbolAddress((void**)&p_cl,  g_ctx_lo);
    cudaGetSymbolAddress((void**)&p_wqh, g_wqkv_hi);
    cudaGetSymbolAddress((void**)&p_wql, g_wqkv_lo);
    cudaGetSymbolAddress((void**)&p_woh, g_wout_hi);
    cudaGetSymbolAddress((void**)&p_wol, g_wout_lo);

    cudaFuncSetAttribute(gemm_mma_kernel<3 * DDM>, cudaFuncAttributeMaxDynamicSharedMemorySize, GEMM_SMEM_BYTES);
    cudaFuncSetAttribute(gemm_mma_kernel<DDM>, cudaFuncAttributeMaxDynamicSharedMemorySize, GEMM_SMEM_BYTES);
    int attn_smem = (int)sizeof(AttnSmem);
    cudaFuncSetAttribute(attn_kernel, cudaFuncAttributeMaxDynamicSharedMemorySize, attn_smem);

    sid_norm_kernel<<<(NT + 255) / 256, 256>>>(seq);
    rope_table_kernel<<<(LL * 32 + 255) / 256, 256>>>();
    wprep_kernel<<<dim3(3 * DDM / 32, DDM / 32), 256>>>(w_qkv, p_wqh, p_wql, 3 * DDM);
    wprep_kernel<<<dim3(DDM / 32, DDM / 32), 256>>>(w_out, p_woh, p_wol, DDM);
    ln_kernel<<<NT, 256>>>(x, ln_w, ln_b);
    gemm_mma_kernel<3 * DDM><<<dim3(3 * DDM / 128, NT / 128), 256, GEMM_SMEM_BYTES>>>(p_xh, p_xl, p_wqh, p_wql, p_qkv);
    qkln_rope_kernel<<<NT, 256>>>(q_ln_w, k_ln_w);
    vprep_kernel<<<dim3(LL / 32, 2, BB * HH), 256>>>();
    attn_kernel<<<dim3(LL / 64, BB * HH), 256, attn_smem>>>();
    gemm_mma_kernel<DDM><<<dim3(DDM / 128, NT / 128), 256, GEMM_SMEM_BYTES>>>(p_ch, p_cl, p_woh, p_wol, out);
}

// round 8
// speedup vs baseline: 2.3953x; 1.0583x over previous
#include <cuda_runtime.h>
#include <cuda_bf16.h>
#include <math.h>
#include <cstdint>

#define BB 4
#define LL 2048
#define DDM 1024
#define HH 16
#define NT (BB*LL)   // 8192 tokens

// ---------------- scratch (device globals: allocation-free rule) ----------------
__device__ float          g_qkv[(size_t)NT * 3 * DDM];      // 96 MB fp32
__device__ __nv_bfloat16  g_x_hi[(size_t)NT * DDM];         // LN output split
__device__ __nv_bfloat16  g_x_lo[(size_t)NT * DDM];
__device__ __nv_bfloat16  g_ctx_hi[(size_t)NT * DDM];       // attention output split
__device__ __nv_bfloat16  g_ctx_lo[(size_t)NT * DDM];
__device__ __nv_bfloat16  g_wqkv_hi[(size_t)3 * DDM * DDM]; // w_qkv^T [3072][1024]
__device__ __nv_bfloat16  g_wqkv_lo[(size_t)3 * DDM * DDM];
__device__ __nv_bfloat16  g_wout_hi[(size_t)DDM * DDM];     // w_out^T [1024][1024]
__device__ __nv_bfloat16  g_wout_lo[(size_t)DDM * DDM];
// head-major attention operands [b,h,l,64] (q,k) and [b,h,dh,l] (vT)
__device__ __nv_bfloat16  g_q_hi[(size_t)NT * 64 * HH];
__device__ __nv_bfloat16  g_q_lo[(size_t)NT * 64 * HH];
__device__ __nv_bfloat16  g_k_hi[(size_t)NT * 64 * HH];
__device__ __nv_bfloat16  g_k_lo[(size_t)NT * 64 * HH];
__device__ __nv_bfloat16  g_vT_hi[(size_t)NT * 64 * HH];
__device__ __nv_bfloat16  g_vT_lo[(size_t)NT * 64 * HH];
__device__ float g_cs[LL * 32];
__device__ float g_sn[LL * 32];
__device__ int   g_sid[NT];

// ---------------- sequence_id dtype sniff + normalize ----------------
__global__ void sid_norm_kernel(const void* __restrict__ seqraw) {
    const int* w = (const int*)seqraw;
    bool is64 = (w[2*1000+1] == 0) && (w[2*1500+1] == 0) && (w[2*2047+1] == 0);
    int i = blockIdx.x * blockDim.x + threadIdx.x;
    if (i < NT) g_sid[i] = is64 ? w[2*i] : w[i];
}

// ---------------- rope tables (fp64 for angle accuracy) ----------------
__global__ void rope_table_kernel() {
    int idx = blockIdx.x * blockDim.x + threadIdx.x;
    if (idx >= LL * 32) return;
    int s = idx >> 5, i = idx & 31;
    double ang = (double)s * pow(10000.0, -(double)i / 32.0);
    g_cs[idx] = (float)cos(ang);
    g_sn[idx] = (float)sin(ang);
}

// ---------------- helpers ----------------
__device__ __forceinline__ uint32_t bf16pack(float a, float b) {
    __nv_bfloat16 ha = __float2bfloat16(a), hb = __float2bfloat16(b);
    uint32_t r = ((uint32_t)*(uint16_t*)&hb << 16) | (uint32_t)*(uint16_t*)&ha;
    return r;
}
__device__ __forceinline__ void mma_bf16(float* d, const uint32_t* a, const uint32_t* b) {
    asm volatile(
        "mma.sync.aligned.m16n8k16.row.col.f32.bf16.bf16.f32 "
        "{%0,%1,%2,%3}, {%4,%5,%6,%7}, {%8,%9}, {%0,%1,%2,%3};"
        : "+f"(d[0]), "+f"(d[1]), "+f"(d[2]), "+f"(d[3])
        : "r"(a[0]), "r"(a[1]), "r"(a[2]), "r"(a[3]), "r"(b[0]), "r"(b[1]));
}
__device__ __forceinline__ void ldsm4(uint32_t* r, uint32_t a) {
    asm volatile("ldmatrix.sync.aligned.m8n8.x4.shared.b16 {%0,%1,%2,%3}, [%4];"
        : "=r"(r[0]), "=r"(r[1]), "=r"(r[2]), "=r"(r[3]) : "r"(a));
}
__device__ __forceinline__ void ldsm2(uint32_t* r, uint32_t a) {
    asm volatile("ldmatrix.sync.aligned.m8n8.x2.shared.b16 {%0,%1}, [%2];"
        : "=r"(r[0]), "=r"(r[1]) : "r"(a));
}
__device__ __forceinline__ uint32_t smem_u32(const void* p) {
    uint32_t a;
    asm("{ .reg .u64 t; cvta.to.shared.u64 t, %1; cvt.u32.u64 %0, t; }" : "=r"(a) : "l"(p));
    return a;
}
__device__ __forceinline__ void cp16(uint32_t dst, const void* src) {
    asm volatile("cp.async.cg.shared.global [%0], [%1], 16;" :: "r"(dst), "l"(src));
}
__device__ __forceinline__ void cp_commit() {
    asm volatile("cp.async.commit_group;" ::: "memory");
}
template<int N>
__device__ __forceinline__ void cp_wait() {
    asm volatile("cp.async.wait_group %0;" :: "n"(N) : "memory");
}

// ---------------- weight prep: transpose [K][N] -> [N][K] + bf16 split ----------------
__global__ void __launch_bounds__(256) wprep_kernel(
    const float* __restrict__ w, __nv_bfloat16* __restrict__ thi,
    __nv_bfloat16* __restrict__ tlo, int N) {
    __shared__ float t[32][33];
    int n0 = blockIdx.x * 32, k0 = blockIdx.y * 32;
    int tx = threadIdx.x & 31, ty = threadIdx.x >> 5;
#pragma unroll
    for (int i = 0; i < 4; i++)
        t[ty + 8*i][tx] = w[(size_t)(k0 + ty + 8*i) * N + n0 + tx];
    __syncthreads();
#pragma unroll
    for (int i = 0; i < 4; i++) {
        float v = t[tx][ty + 8*i];
        __nv_bfloat16 h = __float2bfloat16(v);
        __nv_bfloat16 l = __float2bfloat16(v - __bfloat162float(h));
        size_t o = (size_t)(n0 + ty + 8*i) * 1024 + k0 + tx;
        thi[o] = h; tlo[o] = l;
    }
}

// ---------------- V prep: transpose v[l][dh] -> vT[dh][l] per (b,h) + bf16 split ----------------
__global__ void __launch_bounds__(256) vprep_kernel() {
    __shared__ float t[32][33];
    int l0 = blockIdx.x * 32, d0 = blockIdx.y * 32, bh = blockIdx.z;
    int b = bh >> 4, h = bh & 15;
    int tx = threadIdx.x & 31, ty = threadIdx.x >> 5;
#pragma unroll
    for (int i = 0; i < 4; i++) {
        int l = l0 + ty + 8*i;
        t[ty + 8*i][tx] = g_qkv[((size_t)(b * LL + l)) * 3 * DDM + 2 * DDM + h * 64 + d0 + tx];
    }
    __syncthreads();
#pragma unroll
    for (int i = 0; i < 4; i++) {
        int dh = d0 + ty + 8*i;
        float v = t[tx][ty + 8*i];
        __nv_bfloat16 hh = __float2bfloat16(v);
        __nv_bfloat16 ll = __float2bfloat16(v - __bfloat162float(hh));
        size_t o = ((size_t)bh * 64 + dh) * LL + l0 + tx;
        g_vT_hi[o] = hh; g_vT_lo[o] = ll;
    }
}

// ---------------- input LayerNorm -> bf16 hi/lo split ----------------
__global__ void __launch_bounds__(256) ln_kernel(
    const float* __restrict__ x, const float* __restrict__ w, const float* __restrict__ b) {
    int row = blockIdx.x;
    int tid = threadIdx.x;
    float4 v = ((const float4*)(x + (size_t)row * DDM))[tid];
    float s  = v.x + v.y + v.z + v.w;
    float ss = v.x*v.x + v.y*v.y + v.z*v.z + v.w*v.w;
    __shared__ float rs[8], rss[8];
#pragma unroll
    for (int o = 16; o; o >>= 1) {
        s  += __shfl_xor_sync(0xffffffffu, s,  o);
        ss += __shfl_xor_sync(0xffffffffu, ss, o);
    }
    if ((tid & 31) == 0) { rs[tid >> 5] = s; rss[tid >> 5] = ss; }
    __syncthreads();
    if (tid == 0) {
        float a = 0.f, c = 0.f;
#pragma unroll
        for (int i = 0; i < 8; i++) { a += rs[i]; c += rss[i]; }
        rs[0] = a; rss[0] = c;
    }
    __syncthreads();
    float mean = rs[0] * (1.0f / DDM);
    float var  = rss[0] * (1.0f / DDM) - mean * mean;
    float rstd = rsqrtf(var + 1e-5f);
    float4 wv = ((const float4*)w)[tid];
    float4 bv = ((const float4*)b)[tid];
    float o[4];
    o[0] = (v.x - mean) * rstd * wv.x + bv.x;
    o[1] = (v.y - mean) * rstd * wv.y + bv.y;
    o[2] = (v.z - mean) * rstd * wv.z + bv.z;
    o[3] = (v.w - mean) * rstd * wv.w + bv.w;
    size_t base = (size_t)row * DDM + tid * 4;
    __nv_bfloat16 h[4], l[4];
#pragma unroll
    for (int j = 0; j < 4; j++) {
        h[j] = __float2bfloat16(o[j]);
        l[j] = __float2bfloat16(o[j] - __bfloat162float(h[j]));
    }
    *(uint2*)(g_x_hi + base) = *(uint2*)h;
    *(uint2*)(g_x_lo + base) = *(uint2*)l;
}

// ---------------- tensor GEMM via mma.sync + cp.async pipeline + ldmatrix ----------------
#define SPAD 20
#define ARRW (128 * SPAD)
#define STGW (4 * ARRW)
#define GEMM_SMEM_BYTES (2 * STGW * 4)   // 81920
template<int NN>
__global__ void __launch_bounds__(256) gemm_mma_kernel(
    const __nv_bfloat16* __restrict__ Ahi, const __nv_bfloat16* __restrict__ Alo,
    const __nv_bfloat16* __restrict__ Bhi, const __nv_bfloat16* __restrict__ Blo,
    float* __restrict__ C) {
    extern __shared__ uint32_t sw[];
    const uint32_t sb = smem_u32(sw);
    int tid = threadIdx.x, lane = tid & 31, wid = tid >> 5;
    int m0 = blockIdx.y * 128, n0 = blockIdx.x * 128;
    int wm = (wid & 1) * 64, wn = (wid >> 1) * 32;
    int g = lane >> 2, q = lane & 3;
    int lrow = tid >> 2, lu = tid & 3;
    int lr = lane & 7, sel = lane >> 3;

    uint32_t aoff[4], boff[4];
#pragma unroll
    for (int mf = 0; mf < 4; mf++)
        aoff[mf] = (uint32_t)((wm + mf * 16 + (sel & 1) * 8 + lr) * SPAD + (sel >> 1) * 4) * 4;
#pragma unroll
    for (int nf = 0; nf < 4; nf++)
        boff[nf] = (uint32_t)((wn + nf * 8 + lr) * SPAD + (sel & 1) * 4) * 4;

    float acc[4][4][4] = {};

    auto load_chunk = [&](int kc, int st) {
        uint32_t base = sb + (uint32_t)st * (STGW * 4);
#pragma unroll
        for (int h = 0; h < 2; h++) {
            int row = lrow + h * 64;
            uint32_t so = (uint32_t)(row * SPAD + lu * 4) * 4;
            size_t gA = (size_t)(m0 + row) * 1024 + kc * 32 + lu * 8;
            size_t gB = (size_t)(n0 + row) * 1024 + kc * 32 + lu * 8;
            cp16(base + 0 * ARRW * 4 + so, Ahi + gA);
            cp16(base + 1 * ARRW * 4 + so, Alo + gA);
            cp16(base + 2 * ARRW * 4 + so, Bhi + gB);
            cp16(base + 3 * ARRW * 4 + so, Blo + gB);
        }
    };

    load_chunk(0, 0);
    cp_commit();

    for (int kc = 0; kc < 32; kc++) {
        int st = kc & 1;
        if (kc < 31) { load_chunk(kc + 1, st ^ 1); cp_commit(); cp_wait<1>(); }
        else         { cp_wait<0>(); }
        __syncthreads();
        uint32_t stb = sb + (uint32_t)st * (STGW * 4);
        uint32_t bAh = stb, bAl = stb + ARRW * 4, bBh = stb + 2 * ARRW * 4, bBl = stb + 3 * ARRW * 4;
#pragma unroll
        for (int ks = 0; ks < 2; ks++) {
            uint32_t ko = ks * 32;
            uint32_t ah[4][4], al[4][4], bh[4][2], bl[4][2];
#pragma unroll
            for (int mf = 0; mf < 4; mf++) {
                ldsm4(ah[mf], bAh + aoff[mf] + ko);
                ldsm4(al[mf], bAl + aoff[mf] + ko);
            }
#pragma unroll
            for (int nf = 0; nf < 4; nf++) {
                ldsm2(bh[nf], bBh + boff[nf] + ko);
                ldsm2(bl[nf], bBl + boff[nf] + ko);
            }
#pragma unroll
            for (int mf = 0; mf < 4; mf++)
#pragma unroll
                for (int nf = 0; nf < 4; nf++) {
                    mma_bf16(acc[mf][nf], ah[mf], bh[nf]);
                    mma_bf16(acc[mf][nf], ah[mf], bl[nf]);
                    mma_bf16(acc[mf][nf], al[mf], bh[nf]);
                }
        }
        __syncthreads();
    }
#pragma unroll
    for (int mf = 0; mf < 4; mf++)
#pragma unroll
        for (int nf = 0; nf < 4; nf++) {
            int m = m0 + wm + mf * 16 + g;
            int n = n0 + wn + nf * 8 + q * 2;
            *(float2*)&C[(size_t)m * NN + n]       = make_float2(acc[mf][nf][0], acc[mf][nf][1]);
            *(float2*)&C[(size_t)(m + 8) * NN + n] = make_float2(acc[mf][nf][2], acc[mf][nf][3]);
        }
}

// ---------------- QK LayerNorm + RoPE, q/k passes merged -> head-major bf16 hi/lo ----------------
__global__ void __launch_bounds__(256) qkln_rope_kernel(
    const float* __restrict__ qw, const float* __restrict__ kw) {
    int token = blockIdx.x;
    int tid = threadIdx.x;
    int b = token >> 11, l = token & (LL - 1);
    __shared__ float bufq[DDM], bufk[DDM];
    __shared__ float red[4][8];
    const float* rowq = g_qkv + (size_t)token * 3 * DDM;
    float4 vq = ((const float4*)rowq)[tid];
    float4 vk = ((const float4*)(rowq + DDM))[tid];
    float s0 = vq.x + vq.y + vq.z + vq.w;
    float s1 = vq.x*vq.x + vq.y*vq.y + vq.z*vq.z + vq.w*vq.w;
    float s2 = vk.x + vk.y + vk.z + vk.w;
    float s3 = vk.x*vk.x + vk.y*vk.y + vk.z*vk.z + vk.w*vk.w;
#pragma unroll
    for (int o = 16; o; o >>= 1) {
        s0 += __shfl_xor_sync(0xffffffffu, s0, o);
        s1 += __shfl_xor_sync(0xffffffffu, s1, o);
        s2 += __shfl_xor_sync(0xffffffffu, s2, o);
        s3 += __shfl_xor_sync(0xffffffffu, s3, o);
    }
    if ((tid & 31) == 0) {
        int w = tid >> 5;
        red[0][w] = s0; red[1][w] = s1; red[2][w] = s2; red[3][w] = s3;
    }
    __syncthreads();
    if (tid < 4) {
        float a = 0.f;
#pragma unroll
        for (int i = 0; i < 8; i++) a += red[tid][i];
        red[tid][0] = a;
    }
    __syncthreads();
    float meanq = red[0][0] * (1.0f / DDM);
    float rstdq = rsqrtf(red[1][0] * (1.0f / DDM) - meanq * meanq + 1e-5f);
    float meank = red[2][0] * (1.0f / DDM);
    float rstdk = rsqrtf(red[3][0] * (1.0f / DDM) - meank * meank + 1e-5f);
    float4 wq = ((const float4*)qw)[tid];
    float4 wk = ((const float4*)kw)[tid];
    int c0 = tid * 4;
    bufq[c0 + 0] = (vq.x - meanq) * rstdq * wq.x;
    bufq[c0 + 1] = (vq.y - meanq) * rstdq * wq.y;
    bufq[c0 + 2] = (vq.z - meanq) * rstdq * wq.z;
    bufq[c0 + 3] = (vq.w - meanq) * rstdq * wq.w;
    bufk[c0 + 0] = (vk.x - meank) * rstdk * wk.x;
    bufk[c0 + 1] = (vk.y - meank) * rstdk * wk.y;
    bufk[c0 + 2] = (vk.z - meank) * rstdk * wk.z;
    bufk[c0 + 3] = (vk.w - meank) * rstdk * wk.w;
    __syncthreads();
    __nv_bfloat16 qh[4], ql[4], kh[4], kl[4];
#pragma unroll
    for (int j = 0; j < 4; j++) {
        int c = c0 + j;
        int d = c & 63;
        int i2 = d & 31;
        float cs = g_cs[l * 32 + i2];
        float sn = g_sn[l * 32 + i2];
        float rq = (d < 32) ? -bufq[c + 32] : bufq[c - 32];
        float rk = (d < 32) ? -bufk[c + 32] : bufk[c - 32];
        float oq = bufq[c] * cs + rq * sn;
        float ok = bufk[c] * cs + rk * sn;
        qh[j] = __float2bfloat16(oq);
        ql[j] = __float2bfloat16(oq - __bfloat162float(qh[j]));
        kh[j] = __float2bfloat16(ok);
        kl[j] = __float2bfloat16(ok - __bfloat162float(kh[j]));
    }
    int h = c0 >> 6;
    size_t off = (((size_t)b * HH + h) * LL + l) * 64 + (c0 & 63);
    *(uint2*)(g_q_hi + off) = *(uint2*)qh;
    *(uint2*)(g_q_lo + off) = *(uint2*)ql;
    *(uint2*)(g_k_hi + off) = *(uint2*)kh;
    *(uint2*)(g_k_lo + off) = *(uint2*)kl;
}

// ---------------- tensorized flash attention, 64x64 tiles, active k-range ----------------
#define APAD 36
struct AttnSmem {
    uint32_t Qh[64*APAD], Ql[64*APAD];
    uint32_t Kh[64*APAD], Kl[64*APAD];
    uint32_t Vh[64*APAD], Vl[64*APAD];   // V^T tiles: [dh][l]
    uint32_t Ph[64*APAD], Pl[64*APAD];
    float Ss[64][65];
    float mrow[64], lrow[64], alpha[64];
    int   sidq[64], sidk[64];
    int   ktlo, kthi;
};

__global__ void __launch_bounds__(256) attn_kernel() {
    extern __shared__ char smem_raw[];
    AttnSmem& sm = *(AttnSmem*)smem_raw;
    int tid = threadIdx.x, lane = tid & 31, wid = tid >> 5;
    int wm = (wid & 1) * 32, wn = (wid >> 1) * 16;
    int g = lane >> 2, q = lane & 3;
    int lr = lane & 7, sel = lane >> 3;
    int q0 = blockIdx.x * 64;
    int bh = blockIdx.y;
    int b = bh >> 4;

    uint32_t aoffA[2], boffB[2];
#pragma unroll
    for (int mf = 0; mf < 2; mf++)
        aoffA[mf] = (uint32_t)((wm + mf * 16 + (sel & 1) * 8 + lr) * APAD + (sel >> 1) * 4) * 4;
#pragma unroll
    for (int nf = 0; nf < 2; nf++)
        boffB[nf] = (uint32_t)((wn + nf * 8 + lr) * APAD + (sel & 1) * 4) * 4;

    const uint32_t uQh = smem_u32(sm.Qh), uQl = smem_u32(sm.Ql);
    const uint32_t uKh = smem_u32(sm.Kh), uKl = smem_u32(sm.Kl);
    const uint32_t uVh = smem_u32(sm.Vh), uVl = smem_u32(sm.Vl);
    const uint32_t uPh = smem_u32(sm.Ph), uPl = smem_u32(sm.Pl);

    auto load_tile = [&](uint32_t* dst, const __nv_bfloat16* src, int rstride) {
#pragma unroll
        for (int i = 0; i < 2; i++) {
            int u = tid + i * 256;
            int row = u >> 3, wq = (u & 7) * 4;
            uint4 v = *(const uint4*)(src + (size_t)row * rstride + wq * 2);
            *(uint4*)&dst[row * APAD + wq] = v;
        }
    };

    load_tile(sm.Qh, g_q_hi + ((size_t)bh * LL + q0) * 64, 64);
    load_tile(sm.Ql, g_q_lo + ((size_t)bh * LL + q0) * 64, 64);
    if (tid < 64) {
        sm.sidq[tid] = g_sid[b * LL + q0 + tid];
        sm.mrow[tid] = -INFINITY;
        sm.lrow[tid] = 0.f;
    }
    __syncthreads();

    // sorted ids -> active k-tiles form a contiguous interval; find it with one ballot
    if (tid < 32) {
        int kmin = g_sid[b * LL + tid * 64];
        int kmax = g_sid[b * LL + tid * 64 + 63];
        bool act = (kmax >= sm.sidq[0]) && (kmin <= sm.sidq[63]);
        uint32_t m = __ballot_sync(0xffffffffu, act);
        if (tid == 0) { sm.ktlo = __ffs(m) - 1; sm.kthi = 31 - __clz(m); }
    }
    __syncthreads();
    int ktlo = sm.ktlo, kthi = sm.kthi;

    float O[2][2][4] = {};

    for (int kt = ktlo; kt <= kthi; kt++) {
        if (tid < 64) sm.sidk[tid] = g_sid[b * LL + kt * 64 + tid];
        load_tile(sm.Kh, g_k_hi + ((size_t)bh * LL + kt * 64) * 64, 64);
        load_tile(sm.Kl, g_k_lo + ((size_t)bh * LL + kt * 64) * 64, 64);
        load_tile(sm.Vh, g_vT_hi + (size_t)bh * 64 * LL + kt * 64, LL);
        load_tile(sm.Vl, g_vT_lo + (size_t)bh * 64 * LL + kt * 64, LL);
        __syncthreads();

        // ---- S = Q @ K^T, 3-term bf16 split ----
        float sacc[2][2][4] = {};
#pragma unroll
        for (int ks = 0; ks < 4; ks++) {
            uint32_t ko = ks * 32;
            uint32_t aH[2][4], aL[2][4], bH[2][2], bL[2][2];
#pragma unroll
            for (int mf = 0; mf < 2; mf++) {
                ldsm4(aH[mf], uQh + aoffA[mf] + ko);
                ldsm4(aL[mf], uQl + aoffA[mf] + ko);
            }
#pragma unroll
            for (int nf = 0; nf < 2; nf++) {
                ldsm2(bH[nf], uKh + boffB[nf] + ko);
                ldsm2(bL[nf], uKl + boffB[nf] + ko);
            }
#pragma unroll
            for (int mf = 0; mf < 2; mf++)
#pragma unroll
                for (int nf = 0; nf < 2; nf++) {
                    mma_bf16(sacc[mf][nf], aH[mf], bH[nf]);
                    mma_bf16(sacc[mf][nf], aH[mf], bL[nf]);
                    mma_bf16(sacc[mf][nf], aL[mf], bH[nf]);
                }
        }
#pragma unroll
        for (int mf = 0; mf < 2; mf++)
#pragma unroll
            for (int nf = 0; nf < 2; nf++) {
                int r = wm + mf * 16 + g, c = wn + nf * 8 + 2 * q;
#pragma unroll
                for (int e = 0; e < 4; e++) {
                    int rr = r + (e >> 1) * 8, cc = c + (e & 1);
                    float sv = sacc[mf][nf][e] * 0.125f;
                    if (sm.sidq[rr] != sm.sidk[cc]) sv = -1e30f;
                    sm.Ss[rr][cc] = sv;
                }
            }
        __syncthreads();

        // ---- online softmax: 4 threads per row ----
        {
            int r = tid >> 2, sub = tid & 3;
            float mloc = -INFINITY;
#pragma unroll
            for (int c = sub * 16; c < sub * 16 + 16; c++)
                mloc = fmaxf(mloc, sm.Ss[r][c]);
            mloc = fmaxf(mloc, __shfl_xor_sync(0xffffffffu, mloc, 1));
            mloc = fmaxf(mloc, __shfl_xor_sync(0xffffffffu, mloc, 2));
            float mold = sm.mrow[r];
            float mnew = fmaxf(mold, mloc);
            float ls = 0.f;
#pragma unroll
            for (int w = sub * 8; w < sub * 8 + 8; w++) {
                float p0 = __expf(sm.Ss[r][2 * w]     - mnew);
                float p1 = __expf(sm.Ss[r][2 * w + 1] - mnew);
                ls += p0 + p1;
                float h0 = __bfloat162float(__float2bfloat16(p0));
                float h1 = __bfloat162float(__float2bfloat16(p1));
                sm.Ph[r * APAD + w] = bf16pack(h0, h1);
                sm.Pl[r * APAD + w] = bf16pack(p0 - h0, p1 - h1);
            }
            ls += __shfl_xor_sync(0xffffffffu, ls, 1);
            ls += __shfl_xor_sync(0xffffffffu, ls, 2);
            if (sub == 0) {
                float a = __expf(mold - mnew);
                sm.alpha[r] = a;
                sm.lrow[r] = sm.lrow[r] * a + ls;
                sm.mrow[r] = mnew;
            }
        }
        __syncthreads();

        // ---- O = O*alpha + P @ V, 3-term bf16 split ----
#pragma unroll
        for (int mf = 0; mf < 2; mf++) {
            float a0 = sm.alpha[wm + mf * 16 + g];
            float a1 = sm.alpha[wm + mf * 16 + g + 8];
#pragma unroll
            for (int nf = 0; nf < 2; nf++) {
                O[mf][nf][0] *= a0; O[mf][nf][1] *= a0;
                O[mf][nf][2] *= a1; O[mf][nf][3] *= a1;
            }
        }
#pragma unroll
        for (int ks = 0; ks < 4; ks++) {
            uint32_t ko = ks * 32;
            uint32_t aH[2][4], aL[2][4], bH[2][2], bL[2][2];
#pragma unroll
            for (int mf = 0; mf < 2; mf++) {
                ldsm4(aH[mf], uPh + aoffA[mf] + ko);
                ldsm4(aL[mf], uPl + aoffA[mf] + ko);
            }
#pragma unroll
            for (int nf = 0; nf < 2; nf++) {
                ldsm2(bH[nf], uVh + boffB[nf] + ko);
                ldsm2(bL[nf], uVl + boffB[nf] + ko);
            }
#pragma unroll
            for (int mf = 0; mf < 2; mf++)
#pragma unroll
                for (int nf = 0; nf < 2; nf++) {
                    mma_bf16(O[mf][nf], aH[mf], bH[nf]);
                    mma_bf16(O[mf][nf], aH[mf], bL[nf]);
                    mma_bf16(O[mf][nf], aL[mf], bH[nf]);
                }
        }
        __syncthreads();   // protect K/V/P tiles + sidk before next iteration
    }

    // ---- epilogue: normalize + bf16 hi/lo split for out-projection ----
    int h = bh & 15;
#pragma unroll
    for (int mf = 0; mf < 2; mf++)
#pragma unroll
        for (int nf = 0; nf < 2; nf++) {
            int r = wm + mf * 16 + g, c = wn + nf * 8 + 2 * q;
#pragma unroll
            for (int half = 0; half < 2; half++) {
                int rr = r + half * 8;
                float il = 1.0f / sm.lrow[rr];
                float o0 = O[mf][nf][half * 2 + 0] * il;
                float o1 = O[mf][nf][half * 2 + 1] * il;
                float h0 = __bfloat162float(__float2bfloat16(o0));
                float h1 = __bfloat162float(__float2bfloat16(o1));
                size_t off = ((size_t)(b * LL + q0 + rr)) * DDM + h * 64 + c;
                *(uint32_t*)(g_ctx_hi + off) = bf16pack(h0, h1);
                *(uint32_t*)(g_ctx_lo + off) = bf16pack(o0 - h0, o1 - h1);
            }
        }
}

// ---------------- launch ----------------
extern "C" void kernel_launch(void* const* d_in, const int* in_sizes, int n_in,
                              void* d_out, int out_size) {
    (void)in_sizes; (void)n_in; (void)out_size;
    const float* x      = (const float*)d_in[0];
    const void*  seq    = d_in[1];
    const float* ln_w   = (const float*)d_in[2];
    const float* ln_b   = (const float*)d_in[3];
    const float* w_qkv  = (const float*)d_in[4];
    const float* q_ln_w = (const float*)d_in[5];
    const float* k_ln_w = (const float*)d_in[6];
    const float* w_out  = (const float*)d_in[7];
    float* out = (float*)d_out;

    float* p_qkv;
    __nv_bfloat16 *p_xh, *p_xl, *p_ch, *p_cl, *p_wqh, *p_wql, *p_woh, *p_wol;
    cudaGetSymbolAddress((void**)&p_qkv, g_qkv);
    cudaGetSymbolAddress((void**)&p_xh,  g_x_hi);
    cudaGetSymbolAddress((void**)&p_xl,  g_x_lo);
    cudaGetSymbolAddress((void**)&p_ch,  g_ctx_hi);
    cudaGetSymbolAddress((void**)&p_cl,  g_ctx_lo);
    cudaGetSymbolAddress((void**)&p_wqh, g_wqkv_hi);
    cudaGetSymbolAddress((void**)&p_wql, g_wqkv_lo);
    cudaGetSymbolAddress((void**)&p_woh, g_wout_hi);
    cudaGetSymbolAddress((void**)&p_wol, g_wout_lo);

    cudaFuncSetAttribute(gemm_mma_kernel<3 * DDM>, cudaFuncAttributeMaxDynamicSharedMemorySize, GEMM_SMEM_BYTES);
    cudaFuncSetAttribute(gemm_mma_kernel<DDM>, cudaFuncAttributeMaxDynamicSharedMemorySize, GEMM_SMEM_BYTES);
    int attn_smem = (int)sizeof(AttnSmem);
    cudaFuncSetAttribute(attn_kernel, cudaFuncAttributeMaxDynamicSharedMemorySize, attn_smem);

    sid_norm_kernel<<<(NT + 255) / 256, 256>>>(seq);
    rope_table_kernel<<<(LL * 32 + 255) / 256, 256>>>();
    wprep_kernel<<<dim3(3 * DDM / 32, DDM / 32), 256>>>(w_qkv, p_wqh, p_wql, 3 * DDM);
    wprep_kernel<<<dim3(DDM / 32, DDM / 32), 256>>>(w_out, p_woh, p_wol, DDM);
    ln_kernel<<<NT, 256>>>(x, ln_w, ln_b);
    gemm_mma_kernel<3 * DDM><<<dim3(3 * DDM / 128, NT / 128), 256, GEMM_SMEM_BYTES>>>(p_xh, p_xl, p_wqh, p_wql, p_qkv);
    qkln_rope_kernel<<<NT, 256>>>(q_ln_w, k_ln_w);
    vprep_kernel<<<dim3(LL / 32, 2, BB * HH), 256>>>();
    attn_kernel<<<dim3(LL / 64, BB * HH), 256, attn_smem>>>();
    gemm_mma_kernel<DDM><<<dim3(DDM / 128, NT / 128), 256, GEMM_SMEM_BYTES>>>(p_ch, p_cl, p_woh, p_wol, out);
}